// round 1
// baseline (speedup 1.0000x reference)
#include <cuda_runtime.h>
#include <math.h>

// Problem constants
#define BB   2
#define SS   2048
#define DD   512
#define HH   8
#define HDIM 64
#define FFN  2048
#define LL   4
#define ROWS (BB*SS)   // 4096

// Scratch (no cudaMalloc allowed) ------------------------------------------
__device__ float g_x [ROWS*DD];
__device__ float g_q [ROWS*DD];
__device__ float g_k [ROWS*DD];
__device__ float g_v [ROWS*DD];
__device__ float g_o [ROWS*DD];
__device__ float g_t [ROWS*DD];
__device__ float g_ff[ROWS*FFN];

// ---------------------------------------------------------------------------
// Embedding + sinusoidal positional encoding
// ---------------------------------------------------------------------------
__global__ void embed_pe_kernel(const int* __restrict__ tokens,
                                const float* __restrict__ emb,
                                float* __restrict__ x)
{
    int r = blockIdx.x;           // row in [0, B*S)
    int s = r % SS;               // position
    int tok = tokens[r];
    const float* e = emb + (size_t)tok * DD;
    const float neg_ln1e4_over_d = -logf(10000.0f) / (float)DD;
    for (int i = threadIdx.x; i < DD; i += blockDim.x) {
        float freq = expf((float)(i & ~1) * neg_ln1e4_over_d);
        float ang  = (float)s * freq;
        float pe   = (i & 1) ? cosf(ang) : sinf(ang);
        x[(size_t)r * DD + i] = e[i] + pe;
    }
}

// ---------------------------------------------------------------------------
// SGEMM: C[M,N] = A[M,K] @ B[K,N] (+bias) (+relu)
// BM=BN=128, BK=16, 256 threads, 8x8 micro-tile per thread.
// M,N multiples of 128; K multiple of 16 (holds for all shapes here).
// ---------------------------------------------------------------------------
template<bool BIAS, bool RELU>
__global__ __launch_bounds__(256)
void sgemm_kernel(const float* __restrict__ A,
                  const float* __restrict__ Bm,
                  const float* __restrict__ bias,
                  float* __restrict__ C,
                  int M, int N, int K)
{
    __shared__ __align__(16) float As[16][132];  // A transposed tile, padded
    __shared__ __align__(16) float Bs[16][128];

    const int tid = threadIdx.x;
    const int tx  = tid & 15;         // 0..15
    const int ty  = tid >> 4;         // 0..15
    const int m0  = blockIdx.y * 128;
    const int n0  = blockIdx.x * 128;

    float acc[8][8] = {};

    for (int k0 = 0; k0 < K; k0 += 16) {
        // Load A tile (128x16), store transposed into As[k][m]
        #pragma unroll
        for (int p = 0; p < 2; p++) {
            int e   = tid + p * 256;        // 0..511
            int row = e >> 2;               // 0..127
            int c4  = (e & 3) << 2;         // 0,4,8,12
            float4 va = *(const float4*)&A[(size_t)(m0 + row) * K + k0 + c4];
            As[c4 + 0][row] = va.x;
            As[c4 + 1][row] = va.y;
            As[c4 + 2][row] = va.z;
            As[c4 + 3][row] = va.w;
        }
        // Load B tile (16x128)
        #pragma unroll
        for (int p = 0; p < 2; p++) {
            int e   = tid + p * 256;        // 0..511
            int row = e >> 5;               // 0..15
            int c4  = (e & 31) << 2;        // 0..124
            *(float4*)&Bs[row][c4] =
                *(const float4*)&Bm[(size_t)(k0 + row) * N + n0 + c4];
        }
        __syncthreads();

        #pragma unroll
        for (int kk = 0; kk < 16; kk++) {
            float a[8], b[8];
            *(float4*)(a    ) = *(const float4*)&As[kk][ty * 8];
            *(float4*)(a + 4) = *(const float4*)&As[kk][ty * 8 + 4];
            *(float4*)(b    ) = *(const float4*)&Bs[kk][tx * 8];
            *(float4*)(b + 4) = *(const float4*)&Bs[kk][tx * 8 + 4];
            #pragma unroll
            for (int i = 0; i < 8; i++)
                #pragma unroll
                for (int j = 0; j < 8; j++)
                    acc[i][j] += a[i] * b[j];
        }
        __syncthreads();
    }

    // Epilogue
    #pragma unroll
    for (int i = 0; i < 8; i++) {
        int row = m0 + ty * 8 + i;
        #pragma unroll
        for (int j = 0; j < 8; j += 4) {
            int col = n0 + tx * 8 + j;
            float4 v;
            v.x = acc[i][j + 0];
            v.y = acc[i][j + 1];
            v.z = acc[i][j + 2];
            v.w = acc[i][j + 3];
            if (BIAS) {
                v.x += bias[col + 0];
                v.y += bias[col + 1];
                v.z += bias[col + 2];
                v.w += bias[col + 3];
            }
            if (RELU) {
                v.x = fmaxf(v.x, 0.f);
                v.y = fmaxf(v.y, 0.f);
                v.z = fmaxf(v.z, 0.f);
                v.w = fmaxf(v.w, 0.f);
            }
            *(float4*)&C[(size_t)row * N + col] = v;
        }
    }
}

// ---------------------------------------------------------------------------
// Flash attention (fp32, non-causal). One block = (batch*head, 64-query tile).
// q/k/v/o are [B,S,D] with head h occupying columns [h*64, h*64+64).
// 256 threads as 16x16; each thread owns a 4x4 micro-tile of the 64x64 tiles.
// ---------------------------------------------------------------------------
#define ATTN_SMEM_FLOATS (3*64*65 + 64*64 + 3*64)
#define ATTN_SMEM_BYTES  (ATTN_SMEM_FLOATS * 4)

__global__ __launch_bounds__(256)
void attn_kernel(const float* __restrict__ q,
                 const float* __restrict__ k,
                 const float* __restrict__ v,
                 float* __restrict__ o)
{
    extern __shared__ float sm[];
    float* Qs   = sm;                   // [64][65]
    float* Ks   = Qs + 64 * 65;         // [64][65]
    float* Ps   = Ks + 64 * 65;         // [64][65]
    float* Vs   = Ps + 64 * 65;         // [64][64]
    float* mrow = Vs + 64 * 64;         // [64]
    float* lrow = mrow + 64;            // [64]
    float* arow = lrow + 64;            // [64]

    const int tid = threadIdx.x;
    const int tx  = tid & 15;
    const int ty  = tid >> 4;
    const int q0  = blockIdx.x * 64;
    const int bh  = blockIdx.y;
    const int b   = bh / HH;
    const int h   = bh % HH;
    const size_t base = (size_t)b * SS * DD + (size_t)h * HDIM;

    // Load Q tile (64x64)
    for (int e = tid; e < 64 * 16; e += 256) {
        int rr = e >> 4;
        int c4 = (e & 15) << 2;
        float4 val = *(const float4*)&q[base + (size_t)(q0 + rr) * DD + c4];
        Qs[rr * 65 + c4 + 0] = val.x;
        Qs[rr * 65 + c4 + 1] = val.y;
        Qs[rr * 65 + c4 + 2] = val.z;
        Qs[rr * 65 + c4 + 3] = val.w;
    }
    if (tid < 64) { mrow[tid] = -1e30f; lrow[tid] = 0.0f; }
    __syncthreads();

    float oacc[4][4] = {};
    const float scale = 0.125f;  // 1/sqrt(64)

    for (int t0 = 0; t0 < SS; t0 += 64) {
        // Load K, V tiles
        for (int e = tid; e < 64 * 16; e += 256) {
            int rr = e >> 4;
            int c4 = (e & 15) << 2;
            float4 kv = *(const float4*)&k[base + (size_t)(t0 + rr) * DD + c4];
            Ks[rr * 65 + c4 + 0] = kv.x;
            Ks[rr * 65 + c4 + 1] = kv.y;
            Ks[rr * 65 + c4 + 2] = kv.z;
            Ks[rr * 65 + c4 + 3] = kv.w;
            float4 vv = *(const float4*)&v[base + (size_t)(t0 + rr) * DD + c4];
            *(float4*)&Vs[rr * 64 + c4] = vv;
        }
        __syncthreads();

        // Scores S = Q K^T * scale  (64x64, 4x4 per thread)
        float s[4][4] = {};
        #pragma unroll
        for (int d = 0; d < 64; d++) {
            float a[4], bb[4];
            #pragma unroll
            for (int i = 0; i < 4; i++) a[i]  = Qs[(ty * 4 + i) * 65 + d];
            #pragma unroll
            for (int j = 0; j < 4; j++) bb[j] = Ks[(tx * 4 + j) * 65 + d];
            #pragma unroll
            for (int i = 0; i < 4; i++)
                #pragma unroll
                for (int j = 0; j < 4; j++)
                    s[i][j] += a[i] * bb[j];
        }
        #pragma unroll
        for (int i = 0; i < 4; i++)
            #pragma unroll
            for (int j = 0; j < 4; j++)
                Ps[(ty * 4 + i) * 65 + tx * 4 + j] = s[i][j] * scale;
        __syncthreads();

        // Online softmax row pass: thread tid (<64) owns query row tid
        if (tid < 64) {
            float* pr    = &Ps[tid * 65];
            float  m_old = mrow[tid];
            float  mt    = m_old;
            #pragma unroll 8
            for (int c = 0; c < 64; c++) mt = fmaxf(mt, pr[c]);
            float sum = 0.0f;
            #pragma unroll 8
            for (int c = 0; c < 64; c++) {
                float p = expf(pr[c] - mt);
                pr[c] = p;
                sum += p;
            }
            float alpha = expf(m_old - mt);   // 0 on first tile (m_old = -1e30)
            lrow[tid] = lrow[tid] * alpha + sum;
            mrow[tid] = mt;
            arow[tid] = alpha;
        }
        __syncthreads();

        // Rescale O and accumulate P @ V
        float al[4];
        #pragma unroll
        for (int i = 0; i < 4; i++) al[i] = arow[ty * 4 + i];
        #pragma unroll
        for (int i = 0; i < 4; i++)
            #pragma unroll
            for (int j = 0; j < 4; j++)
                oacc[i][j] *= al[i];

        #pragma unroll
        for (int kk = 0; kk < 64; kk++) {
            float p[4], vv[4];
            #pragma unroll
            for (int i = 0; i < 4; i++) p[i]  = Ps[(ty * 4 + i) * 65 + kk];
            #pragma unroll
            for (int j = 0; j < 4; j++) vv[j] = Vs[kk * 64 + tx * 4 + j];
            #pragma unroll
            for (int i = 0; i < 4; i++)
                #pragma unroll
                for (int j = 0; j < 4; j++)
                    oacc[i][j] += p[i] * vv[j];
        }
        __syncthreads();
    }

    // Normalize and write
    float linv[4];
    #pragma unroll
    for (int i = 0; i < 4; i++) linv[i] = 1.0f / lrow[ty * 4 + i];
    #pragma unroll
    for (int i = 0; i < 4; i++) {
        int row = q0 + ty * 4 + i;
        #pragma unroll
        for (int j = 0; j < 4; j++)
            o[base + (size_t)row * DD + tx * 4 + j] = oacc[i][j] * linv[i];
    }
}

// ---------------------------------------------------------------------------
// out[r,:] = LayerNorm(a[r,:] + b[r,:]) * g + beta     (D = 512, 256 threads)
// ---------------------------------------------------------------------------
__global__ __launch_bounds__(256)
void add_ln_kernel(const float* __restrict__ a,
                   const float* __restrict__ b,
                   const float* __restrict__ g,
                   const float* __restrict__ beta,
                   float* __restrict__ out)
{
    __shared__ float red[256];
    const int tid = threadIdx.x;
    const size_t r = blockIdx.x;

    float v0 = a[r * DD + tid]       + b[r * DD + tid];
    float v1 = a[r * DD + tid + 256] + b[r * DD + tid + 256];

    red[tid] = v0 + v1;
    __syncthreads();
    #pragma unroll
    for (int off = 128; off > 0; off >>= 1) {
        if (tid < off) red[tid] += red[tid + off];
        __syncthreads();
    }
    float mean = red[0] * (1.0f / (float)DD);
    __syncthreads();

    float d0 = v0 - mean, d1 = v1 - mean;
    red[tid] = d0 * d0 + d1 * d1;
    __syncthreads();
    #pragma unroll
    for (int off = 128; off > 0; off >>= 1) {
        if (tid < off) red[tid] += red[tid + off];
        __syncthreads();
    }
    float var  = red[0] * (1.0f / (float)DD);
    float rstd = rsqrtf(var + 1e-5f);

    out[r * DD + tid]       = d0 * rstd * g[tid]       + beta[tid];
    out[r * DD + tid + 256] = d1 * rstd * g[tid + 256] + beta[tid + 256];
}

// ---------------------------------------------------------------------------
// Launcher
// ---------------------------------------------------------------------------
extern "C" void kernel_launch(void* const* d_in, const int* in_sizes, int n_in,
                              void* d_out, int out_size)
{
    (void)in_sizes; (void)n_in; (void)out_size;

    const int*   tokens = (const int*)  d_in[0];
    const float* emb    = (const float*)d_in[1];
    const float* wq     = (const float*)d_in[2];
    const float* wk     = (const float*)d_in[3];
    const float* wv     = (const float*)d_in[4];
    const float* wo     = (const float*)d_in[5];
    const float* w1     = (const float*)d_in[6];
    const float* bf1    = (const float*)d_in[7];
    const float* w2     = (const float*)d_in[8];
    const float* bf2    = (const float*)d_in[9];
    const float* ln1g   = (const float*)d_in[10];
    const float* ln1b   = (const float*)d_in[11];
    const float* ln2g   = (const float*)d_in[12];
    const float* ln2b   = (const float*)d_in[13];
    float* out = (float*)d_out;

    float *x, *q, *k, *v, *o, *t, *ff;
    cudaGetSymbolAddress((void**)&x,  g_x);
    cudaGetSymbolAddress((void**)&q,  g_q);
    cudaGetSymbolAddress((void**)&k,  g_k);
    cudaGetSymbolAddress((void**)&v,  g_v);
    cudaGetSymbolAddress((void**)&o,  g_o);
    cudaGetSymbolAddress((void**)&t,  g_t);
    cudaGetSymbolAddress((void**)&ff, g_ff);

    cudaFuncSetAttribute(attn_kernel,
                         cudaFuncAttributeMaxDynamicSharedMemorySize,
                         ATTN_SMEM_BYTES);

    embed_pe_kernel<<<ROWS, 256>>>(tokens, emb, x);

    const dim3 gD(DD  / 128, ROWS / 128);   // (4, 32)
    const dim3 gF(FFN / 128, ROWS / 128);   // (16, 32)
    const dim3 gA(SS / 64, BB * HH);        // (32, 16)

    for (int l = 0; l < LL; l++) {
        const float* Wq = wq + (size_t)l * DD * DD;
        const float* Wk = wk + (size_t)l * DD * DD;
        const float* Wv = wv + (size_t)l * DD * DD;
        const float* Wo = wo + (size_t)l * DD * DD;
        const float* W1 = w1 + (size_t)l * DD * FFN;
        const float* B1 = bf1 + (size_t)l * FFN;
        const float* W2 = w2 + (size_t)l * FFN * DD;
        const float* B2 = bf2 + (size_t)l * DD;

        sgemm_kernel<false, false><<<gD, 256>>>(x, Wq, nullptr, q, ROWS, DD, DD);
        sgemm_kernel<false, false><<<gD, 256>>>(x, Wk, nullptr, k, ROWS, DD, DD);
        sgemm_kernel<false, false><<<gD, 256>>>(x, Wv, nullptr, v, ROWS, DD, DD);

        attn_kernel<<<gA, 256, ATTN_SMEM_BYTES>>>(q, k, v, o);

        sgemm_kernel<false, false><<<gD, 256>>>(o, Wo, nullptr, t, ROWS, DD, DD);
        add_ln_kernel<<<ROWS, 256>>>(t, x, ln1g + (size_t)l * DD, ln1b + (size_t)l * DD, x);

        sgemm_kernel<true, true ><<<gF, 256>>>(x,  W1, B1, ff, ROWS, FFN, DD);
        sgemm_kernel<true, false><<<gD, 256>>>(ff, W2, B2, t,  ROWS, DD, FFN);

        float* ln2_out = (l == LL - 1) ? out : x;
        add_ln_kernel<<<ROWS, 256>>>(t, x, ln2g + (size_t)l * DD, ln2b + (size_t)l * DD, ln2_out);
    }
}

// round 3
// speedup vs baseline: 1.5306x; 1.5306x over previous
#include <cuda_runtime.h>
#include <cuda_bf16.h>
#include <math.h>
#include <stdint.h>

// Problem constants
#define BB   2
#define SS   2048
#define DD   512
#define HH   8
#define HDIM 64
#define FFN  2048
#define LL   4
#define ROWS (BB*SS)   // 4096

// ---------------------------------------------------------------------------
// Scratch (no cudaMalloc allowed)
// ---------------------------------------------------------------------------
__device__ float g_x  [ROWS*DD];
__device__ float g_qkv[ROWS*3*DD];
__device__ float g_o  [ROWS*DD];
__device__ float g_t  [ROWS*DD];
__device__ float g_ff [ROWS*FFN];

__device__ __nv_bfloat16 g_ahi[ROWS*FFN];
__device__ __nv_bfloat16 g_alo[ROWS*FFN];

__device__ __nv_bfloat16 g_wqkv_hi[3*DD*DD], g_wqkv_lo[3*DD*DD];
__device__ __nv_bfloat16 g_wo_hi  [DD*DD],   g_wo_lo  [DD*DD];
__device__ __nv_bfloat16 g_w1_hi  [FFN*DD],  g_w1_lo  [FFN*DD];
__device__ __nv_bfloat16 g_w2_hi  [DD*FFN],  g_w2_lo  [DD*FFN];

// ---------------------------------------------------------------------------
// PTX helpers (compute_103-safe: cp.async / ldmatrix / mma.sync only)
// ---------------------------------------------------------------------------
__device__ __forceinline__ uint32_t smem_u32(const void* p) {
    uint32_t a;
    asm("{ .reg .u64 t; cvta.to.shared.u64 t, %1; cvt.u32.u64 %0, t; }"
        : "=r"(a) : "l"(p));
    return a;
}

__device__ __forceinline__ void cpa16(uint32_t saddr, const void* gaddr) {
    asm volatile("cp.async.ca.shared.global [%0], [%1], 16;"
                 :: "r"(saddr), "l"(gaddr) : "memory");
}
__device__ __forceinline__ void cpa_commit() {
    asm volatile("cp.async.commit_group;" ::: "memory");
}
__device__ __forceinline__ void cpa_wait1() {
    asm volatile("cp.async.wait_group 1;" ::: "memory");
}
__device__ __forceinline__ void cpa_wait0() {
    asm volatile("cp.async.wait_group 0;" ::: "memory");
}

__device__ __forceinline__ void ldm_x4(uint32_t* r, uint32_t addr) {
    asm volatile("ldmatrix.sync.aligned.m8n8.x4.shared.b16 {%0,%1,%2,%3}, [%4];"
                 : "=r"(r[0]), "=r"(r[1]), "=r"(r[2]), "=r"(r[3]) : "r"(addr));
}

__device__ __forceinline__ void mma_bf16(float* c, const uint32_t* a,
                                         uint32_t b0, uint32_t b1) {
    asm volatile(
        "mma.sync.aligned.m16n8k16.row.col.f32.bf16.bf16.f32 "
        "{%0,%1,%2,%3}, {%4,%5,%6,%7}, {%8,%9}, {%0,%1,%2,%3};"
        : "+f"(c[0]), "+f"(c[1]), "+f"(c[2]), "+f"(c[3])
        : "r"(a[0]), "r"(a[1]), "r"(a[2]), "r"(a[3]), "r"(b0), "r"(b1));
}

// ---------------------------------------------------------------------------
// Embedding + sinusoidal positional encoding
// ---------------------------------------------------------------------------
__global__ void embed_pe_kernel(const int* __restrict__ tokens,
                                const float* __restrict__ emb,
                                float* __restrict__ x)
{
    int r = blockIdx.x;
    int s = r % SS;
    int tok = tokens[r];
    const float* e = emb + (size_t)tok * DD;
    const float neg_ln1e4_over_d = -logf(10000.0f) / (float)DD;
    for (int i = threadIdx.x; i < DD; i += blockDim.x) {
        float freq = expf((float)(i & ~1) * neg_ln1e4_over_d);
        float ang  = (float)s * freq;
        float pe   = (i & 1) ? cosf(ang) : sinf(ang);
        x[(size_t)r * DD + i] = e[i] + pe;
    }
}

// ---------------------------------------------------------------------------
// Weight transpose + bf16 hi/lo split: W[K,N] fp32 -> T_hi/T_lo [N,K] bf16
// ---------------------------------------------------------------------------
__global__ void transpose_split_kernel(const float* __restrict__ W,
                                       __nv_bfloat16* __restrict__ Thi,
                                       __nv_bfloat16* __restrict__ Tlo,
                                       int K, int N)
{
    __shared__ float tile[32][33];
    const int k0 = blockIdx.y * 32;
    const int n0 = blockIdx.x * 32;
    const int tx = threadIdx.x;
    const int ty = threadIdx.y;

    #pragma unroll
    for (int i = ty; i < 32; i += 8)
        tile[i][tx] = W[(size_t)(k0 + i) * N + n0 + tx];
    __syncthreads();
    #pragma unroll
    for (int i = ty; i < 32; i += 8) {
        float v = tile[tx][i];
        __nv_bfloat16 h = __float2bfloat16(v);
        __nv_bfloat16 l = __float2bfloat16(v - __bfloat162float(h));
        Thi[(size_t)(n0 + i) * K + k0 + tx] = h;
        Tlo[(size_t)(n0 + i) * K + k0 + tx] = l;
    }
}

// ---------------------------------------------------------------------------
// Activation bf16 hi/lo split (elementwise, float4 path)
// ---------------------------------------------------------------------------
__global__ void split_kernel(const float* __restrict__ x,
                             __nv_bfloat16* __restrict__ hi,
                             __nv_bfloat16* __restrict__ lo,
                             int n4)
{
    int i = blockIdx.x * blockDim.x + threadIdx.x;
    if (i >= n4) return;
    float4 v = ((const float4*)x)[i];
    __nv_bfloat16 h0 = __float2bfloat16(v.x);
    __nv_bfloat16 h1 = __float2bfloat16(v.y);
    __nv_bfloat16 h2 = __float2bfloat16(v.z);
    __nv_bfloat16 h3 = __float2bfloat16(v.w);
    __nv_bfloat16 l0 = __float2bfloat16(v.x - __bfloat162float(h0));
    __nv_bfloat16 l1 = __float2bfloat16(v.y - __bfloat162float(h1));
    __nv_bfloat16 l2 = __float2bfloat16(v.z - __bfloat162float(h2));
    __nv_bfloat16 l3 = __float2bfloat16(v.w - __bfloat162float(h3));
    ((__nv_bfloat162*)hi)[2*i+0] = __halves2bfloat162(h0, h1);
    ((__nv_bfloat162*)hi)[2*i+1] = __halves2bfloat162(h2, h3);
    ((__nv_bfloat162*)lo)[2*i+0] = __halves2bfloat162(l0, l1);
    ((__nv_bfloat162*)lo)[2*i+1] = __halves2bfloat162(l2, l3);
}

// ---------------------------------------------------------------------------
// bf16x3 GEMM via mma.sync: C[M,N] = A[M,K] @ B^T  (B stored [N,K] K-major)
// CTA 128x128, BK=32, 4 warps (each 64x64), double-buffered cp.async.
// Passes: Ahi*Bhi + Ahi*Blo + Alo*Bhi  (fp32 accumulate).
// ---------------------------------------------------------------------------
#define GM_PITCH_B   80                       // bytes per smem row (32 bf16 + pad)
#define GM_TILE_B    (128 * GM_PITCH_B)       // 10240
#define GM_STAGE_B   (4 * GM_TILE_B)          // 40960  (Ah, Al, Bh, Bl)
#define GM_SMEM_B    (2 * GM_STAGE_B)         // 81920

__device__ __forceinline__ void gm_load_stage(uint32_t sb, int stage,
                                              const __nv_bfloat16* __restrict__ Ahi,
                                              const __nv_bfloat16* __restrict__ Alo,
                                              const __nv_bfloat16* __restrict__ Bhi,
                                              const __nv_bfloat16* __restrict__ Blo,
                                              int m0, int n0, int kc, int K, int tid)
{
    const uint32_t sbase = sb + stage * GM_STAGE_B;
    #pragma unroll
    for (int t = 0; t < 4; t++) {
        const __nv_bfloat16* p = (t == 0) ? Ahi : (t == 1) ? Alo : (t == 2) ? Bhi : Blo;
        const int rb = (t < 2) ? m0 : n0;
        #pragma unroll
        for (int i = 0; i < 4; i++) {
            int e   = tid + i * 128;         // 0..511
            int row = e >> 2;                // 0..127
            int ch  = e & 3;                 // 16B chunk within 64B row
            cpa16(sbase + t * GM_TILE_B + row * GM_PITCH_B + ch * 16,
                  p + (size_t)(rb + row) * K + kc + ch * 8);
        }
    }
    cpa_commit();
}

template<bool BIAS, bool RELU>
__global__ __launch_bounds__(128, 2)
void gemm_mma_kernel(const __nv_bfloat16* __restrict__ Ahi,
                     const __nv_bfloat16* __restrict__ Alo,
                     const __nv_bfloat16* __restrict__ Bhi,
                     const __nv_bfloat16* __restrict__ Blo,
                     const float* __restrict__ bias,
                     float* __restrict__ C,
                     int M, int N, int K)
{
    extern __shared__ char smem[];
    const uint32_t sb = smem_u32(smem);
    const int tid  = threadIdx.x;
    const int lane = tid & 31;
    const int wid  = tid >> 5;
    const int wm   = wid & 1;          // 0..1 (64 rows each)
    const int wn   = wid >> 1;         // 0..1 (64 cols each)
    const int m0   = blockIdx.y * 128;
    const int n0   = blockIdx.x * 128;

    float cc[4][8][4];
    #pragma unroll
    for (int mt = 0; mt < 4; mt++)
        #pragma unroll
        for (int nt = 0; nt < 8; nt++)
            #pragma unroll
            for (int j = 0; j < 4; j++)
                cc[mt][nt][j] = 0.0f;

    const int NC = K >> 5;   // BK = 32

    gm_load_stage(sb, 0, Ahi, Alo, Bhi, Blo, m0, n0, 0, K, tid);

    // Per-warp ldmatrix base offsets
    const int a_row_off = (lane & 15);                 // row within mtile
    const int a_col_off = ((lane >> 4) << 3);          // 0 or 8 (bf16)
    const int b_row_off = (lane & 7) + ((lane >> 4) << 3);
    const int b_col_off = (((lane >> 3) & 1) << 3);

    for (int c = 0; c < NC; c++) {
        const int s = c & 1;
        if (c + 1 < NC) {
            gm_load_stage(sb, s ^ 1, Ahi, Alo, Bhi, Blo, m0, n0, (c + 1) << 5, K, tid);
            cpa_wait1();
        } else {
            cpa_wait0();
        }
        __syncthreads();

        const uint32_t ah_b = sb + s * GM_STAGE_B + 0 * GM_TILE_B;
        const uint32_t al_b = sb + s * GM_STAGE_B + 1 * GM_TILE_B;
        const uint32_t bh_b = sb + s * GM_STAGE_B + 2 * GM_TILE_B;
        const uint32_t bl_b = sb + s * GM_STAGE_B + 3 * GM_TILE_B;

        #pragma unroll
        for (int ks = 0; ks < 2; ks++) {
            uint32_t ah[4][4], al[4][4], bh[4][4], bl[4][4];
            const int acol = (ks * 16 + a_col_off) * 2;  // bytes
            const int bcol = (ks * 16 + b_col_off) * 2;
            #pragma unroll
            for (int mt = 0; mt < 4; mt++) {
                const int r = (wm * 64 + mt * 16 + a_row_off) * GM_PITCH_B;
                ldm_x4(ah[mt], ah_b + r + acol);
                ldm_x4(al[mt], al_b + r + acol);
            }
            #pragma unroll
            for (int ng = 0; ng < 4; ng++) {
                const int r = (wn * 64 + ng * 16 + b_row_off) * GM_PITCH_B;
                ldm_x4(bh[ng], bh_b + r + bcol);
                ldm_x4(bl[ng], bl_b + r + bcol);
            }
            #pragma unroll
            for (int mt = 0; mt < 4; mt++)
                #pragma unroll
                for (int nt = 0; nt < 8; nt++) {
                    const int ng = nt >> 1, o = (nt & 1) * 2;
                    mma_bf16(cc[mt][nt], ah[mt], bh[ng][o], bh[ng][o + 1]);
                    mma_bf16(cc[mt][nt], ah[mt], bl[ng][o], bl[ng][o + 1]);
                    mma_bf16(cc[mt][nt], al[mt], bh[ng][o], bh[ng][o + 1]);
                }
        }
        __syncthreads();
    }

    // Epilogue
    #pragma unroll
    for (int mt = 0; mt < 4; mt++) {
        const int r0 = m0 + wm * 64 + mt * 16 + (lane >> 2);
        #pragma unroll
        for (int nt = 0; nt < 8; nt++) {
            const int col = n0 + wn * 64 + nt * 8 + (lane & 3) * 2;
            float2 v0 = make_float2(cc[mt][nt][0], cc[mt][nt][1]);
            float2 v1 = make_float2(cc[mt][nt][2], cc[mt][nt][3]);
            if (BIAS) {
                float b0 = bias[col], b1 = bias[col + 1];
                v0.x += b0; v0.y += b1;
                v1.x += b0; v1.y += b1;
            }
            if (RELU) {
                v0.x = fmaxf(v0.x, 0.f); v0.y = fmaxf(v0.y, 0.f);
                v1.x = fmaxf(v1.x, 0.f); v1.y = fmaxf(v1.y, 0.f);
            }
            *(float2*)&C[(size_t)r0 * N + col]       = v0;
            *(float2*)&C[(size_t)(r0 + 8) * N + col] = v1;
        }
    }
}

// ---------------------------------------------------------------------------
// Flash attention (fp32, non-causal). qkv packed [B,S,3*D]; o is [B,S,D].
// ---------------------------------------------------------------------------
#define LDQKV (3*DD)
#define ATTN_SMEM_FLOATS (3*64*65 + 64*64 + 3*64)
#define ATTN_SMEM_BYTES  (ATTN_SMEM_FLOATS * 4)

__global__ __launch_bounds__(256)
void attn_kernel(const float* __restrict__ qkv,
                 float* __restrict__ o)
{
    extern __shared__ float sm[];
    float* Qs   = sm;
    float* Ks   = Qs + 64 * 65;
    float* Ps   = Ks + 64 * 65;
    float* Vs   = Ps + 64 * 65;
    float* mrow = Vs + 64 * 64;
    float* lrow = mrow + 64;
    float* arow = lrow + 64;

    const int tid = threadIdx.x;
    const int tx  = tid & 15;
    const int ty  = tid >> 4;
    const int q0  = blockIdx.x * 64;
    const int bh  = blockIdx.y;
    const int b   = bh / HH;
    const int h   = bh % HH;
    const size_t baseq = (size_t)b * SS * LDQKV + (size_t)h * HDIM;
    const size_t basek = baseq + DD;
    const size_t basev = baseq + 2 * DD;
    const size_t baseo = (size_t)b * SS * DD + (size_t)h * HDIM;

    for (int e = tid; e < 64 * 16; e += 256) {
        int rr = e >> 4;
        int c4 = (e & 15) << 2;
        float4 val = *(const float4*)&qkv[baseq + (size_t)(q0 + rr) * LDQKV + c4];
        Qs[rr * 65 + c4 + 0] = val.x;
        Qs[rr * 65 + c4 + 1] = val.y;
        Qs[rr * 65 + c4 + 2] = val.z;
        Qs[rr * 65 + c4 + 3] = val.w;
    }
    if (tid < 64) { mrow[tid] = -1e30f; lrow[tid] = 0.0f; }
    __syncthreads();

    float oacc[4][4] = {};
    const float scale = 0.125f;

    for (int t0 = 0; t0 < SS; t0 += 64) {
        for (int e = tid; e < 64 * 16; e += 256) {
            int rr = e >> 4;
            int c4 = (e & 15) << 2;
            float4 kv = *(const float4*)&qkv[basek + (size_t)(t0 + rr) * LDQKV + c4];
            Ks[rr * 65 + c4 + 0] = kv.x;
            Ks[rr * 65 + c4 + 1] = kv.y;
            Ks[rr * 65 + c4 + 2] = kv.z;
            Ks[rr * 65 + c4 + 3] = kv.w;
            float4 vv = *(const float4*)&qkv[basev + (size_t)(t0 + rr) * LDQKV + c4];
            *(float4*)&Vs[rr * 64 + c4] = vv;
        }
        __syncthreads();

        float s[4][4] = {};
        #pragma unroll
        for (int d = 0; d < 64; d++) {
            float a[4], bb[4];
            #pragma unroll
            for (int i = 0; i < 4; i++) a[i]  = Qs[(ty * 4 + i) * 65 + d];
            #pragma unroll
            for (int j = 0; j < 4; j++) bb[j] = Ks[(tx * 4 + j) * 65 + d];
            #pragma unroll
            for (int i = 0; i < 4; i++)
                #pragma unroll
                for (int j = 0; j < 4; j++)
                    s[i][j] += a[i] * bb[j];
        }
        #pragma unroll
        for (int i = 0; i < 4; i++)
            #pragma unroll
            for (int j = 0; j < 4; j++)
                Ps[(ty * 4 + i) * 65 + tx * 4 + j] = s[i][j] * scale;
        __syncthreads();

        if (tid < 64) {
            float* pr    = &Ps[tid * 65];
            float  m_old = mrow[tid];
            float  mt    = m_old;
            #pragma unroll 8
            for (int c = 0; c < 64; c++) mt = fmaxf(mt, pr[c]);
            float sum = 0.0f;
            #pragma unroll 8
            for (int c = 0; c < 64; c++) {
                float p = expf(pr[c] - mt);
                pr[c] = p;
                sum += p;
            }
            float alpha = expf(m_old - mt);
            lrow[tid] = lrow[tid] * alpha + sum;
            mrow[tid] = mt;
            arow[tid] = alpha;
        }
        __syncthreads();

        float al[4];
        #pragma unroll
        for (int i = 0; i < 4; i++) al[i] = arow[ty * 4 + i];
        #pragma unroll
        for (int i = 0; i < 4; i++)
            #pragma unroll
            for (int j = 0; j < 4; j++)
                oacc[i][j] *= al[i];

        #pragma unroll
        for (int kk = 0; kk < 64; kk++) {
            float p[4], vv[4];
            #pragma unroll
            for (int i = 0; i < 4; i++) p[i]  = Ps[(ty * 4 + i) * 65 + kk];
            #pragma unroll
            for (int j = 0; j < 4; j++) vv[j] = Vs[kk * 64 + tx * 4 + j];
            #pragma unroll
            for (int i = 0; i < 4; i++)
                #pragma unroll
                for (int j = 0; j < 4; j++)
                    oacc[i][j] += p[i] * vv[j];
        }
        __syncthreads();
    }

    float linv[4];
    #pragma unroll
    for (int i = 0; i < 4; i++) linv[i] = 1.0f / lrow[ty * 4 + i];
    #pragma unroll
    for (int i = 0; i < 4; i++) {
        int row = q0 + ty * 4 + i;
        #pragma unroll
        for (int j = 0; j < 4; j++)
            o[baseo + (size_t)row * DD + tx * 4 + j] = oacc[i][j] * linv[i];
    }
}

// ---------------------------------------------------------------------------
// out[r,:] = LayerNorm(a[r,:] + b[r,:]) * g + beta
// ---------------------------------------------------------------------------
__global__ __launch_bounds__(256)
void add_ln_kernel(const float* __restrict__ a,
                   const float* __restrict__ b,
                   const float* __restrict__ g,
                   const float* __restrict__ beta,
                   float* __restrict__ out)
{
    __shared__ float red[256];
    const int tid = threadIdx.x;
    const size_t r = blockIdx.x;

    float v0 = a[r * DD + tid]       + b[r * DD + tid];
    float v1 = a[r * DD + tid + 256] + b[r * DD + tid + 256];

    red[tid] = v0 + v1;
    __syncthreads();
    #pragma unroll
    for (int off = 128; off > 0; off >>= 1) {
        if (tid < off) red[tid] += red[tid + off];
        __syncthreads();
    }
    float mean = red[0] * (1.0f / (float)DD);
    __syncthreads();

    float d0 = v0 - mean, d1 = v1 - mean;
    red[tid] = d0 * d0 + d1 * d1;
    __syncthreads();
    #pragma unroll
    for (int off = 128; off > 0; off >>= 1) {
        if (tid < off) red[tid] += red[tid + off];
        __syncthreads();
    }
    float var  = red[0] * (1.0f / (float)DD);
    float rstd = rsqrtf(var + 1e-5f);

    out[r * DD + tid]       = d0 * rstd * g[tid]       + beta[tid];
    out[r * DD + tid + 256] = d1 * rstd * g[tid + 256] + beta[tid + 256];
}

// ---------------------------------------------------------------------------
// Launcher
// ---------------------------------------------------------------------------
extern "C" void kernel_launch(void* const* d_in, const int* in_sizes, int n_in,
                              void* d_out, int out_size)
{
    (void)in_sizes; (void)n_in; (void)out_size;

    const int*   tokens = (const int*)  d_in[0];
    const float* emb    = (const float*)d_in[1];
    const float* wq     = (const float*)d_in[2];
    const float* wk     = (const float*)d_in[3];
    const float* wv     = (const float*)d_in[4];
    const float* wo     = (const float*)d_in[5];
    const float* w1     = (const float*)d_in[6];
    const float* bf1    = (const float*)d_in[7];
    const float* w2     = (const float*)d_in[8];
    const float* bf2    = (const float*)d_in[9];
    const float* ln1g   = (const float*)d_in[10];
    const float* ln1b   = (const float*)d_in[11];
    const float* ln2g   = (const float*)d_in[12];
    const float* ln2b   = (const float*)d_in[13];
    float* out = (float*)d_out;

    float *x, *qkv, *o, *t, *ff;
    __nv_bfloat16 *ahi, *alo, *wqkvh, *wqkvl, *woh, *wol, *w1h, *w1l, *w2h, *w2l;
    cudaGetSymbolAddress((void**)&x,    g_x);
    cudaGetSymbolAddress((void**)&qkv,  g_qkv);
    cudaGetSymbolAddress((void**)&o,    g_o);
    cudaGetSymbolAddress((void**)&t,    g_t);
    cudaGetSymbolAddress((void**)&ff,   g_ff);
    cudaGetSymbolAddress((void**)&ahi,  g_ahi);
    cudaGetSymbolAddress((void**)&alo,  g_alo);
    cudaGetSymbolAddress((void**)&wqkvh, g_wqkv_hi);
    cudaGetSymbolAddress((void**)&wqkvl, g_wqkv_lo);
    cudaGetSymbolAddress((void**)&woh,  g_wo_hi);
    cudaGetSymbolAddress((void**)&wol,  g_wo_lo);
    cudaGetSymbolAddress((void**)&w1h,  g_w1_hi);
    cudaGetSymbolAddress((void**)&w1l,  g_w1_lo);
    cudaGetSymbolAddress((void**)&w2h,  g_w2_hi);
    cudaGetSymbolAddress((void**)&w2l,  g_w2_lo);

    cudaFuncSetAttribute(attn_kernel,
                         cudaFuncAttributeMaxDynamicSharedMemorySize, ATTN_SMEM_BYTES);
    cudaFuncSetAttribute(gemm_mma_kernel<false, false>,
                         cudaFuncAttributeMaxDynamicSharedMemorySize, GM_SMEM_B);
    cudaFuncSetAttribute(gemm_mma_kernel<true, true>,
                         cudaFuncAttributeMaxDynamicSharedMemorySize, GM_SMEM_B);
    cudaFuncSetAttribute(gemm_mma_kernel<true, false>,
                         cudaFuncAttributeMaxDynamicSharedMemorySize, GM_SMEM_B);

    embed_pe_kernel<<<ROWS, 256>>>(tokens, emb, x);

    const dim3 tsB(32, 8);
    const dim3 gQKV(3 * DD / 128, ROWS / 128);  // (12, 32)
    const dim3 gD(DD / 128, ROWS / 128);        // (4, 32)
    const dim3 gF(FFN / 128, ROWS / 128);       // (16, 32)
    const dim3 gA(SS / 64, BB * HH);            // (32, 16)

    const int n4_x  = ROWS * DD / 4;
    const int n4_ff = ROWS * FFN / 4;

    for (int l = 0; l < LL; l++) {
        const float* Wq = wq + (size_t)l * DD * DD;
        const float* Wk = wk + (size_t)l * DD * DD;
        const float* Wv = wv + (size_t)l * DD * DD;
        const float* Wo = wo + (size_t)l * DD * DD;
        const float* W1 = w1 + (size_t)l * DD * FFN;
        const float* B1 = bf1 + (size_t)l * FFN;
        const float* W2 = w2 + (size_t)l * FFN * DD;
        const float* B2 = bf2 + (size_t)l * DD;

        // Weight prep: transpose + split ([K,N] fp32 -> [N,K] bf16 hi/lo)
        transpose_split_kernel<<<dim3(16, 16), tsB>>>(Wq, wqkvh,           wqkvl,           DD, DD);
        transpose_split_kernel<<<dim3(16, 16), tsB>>>(Wk, wqkvh + DD*DD,   wqkvl + DD*DD,   DD, DD);
        transpose_split_kernel<<<dim3(16, 16), tsB>>>(Wv, wqkvh + 2*DD*DD, wqkvl + 2*DD*DD, DD, DD);
        transpose_split_kernel<<<dim3(16, 16), tsB>>>(Wo, woh,             wol,             DD, DD);
        transpose_split_kernel<<<dim3(64, 16), tsB>>>(W1, w1h,             w1l,             DD, FFN);
        transpose_split_kernel<<<dim3(16, 64), tsB>>>(W2, w2h,             w2l,             FFN, DD);

        // Fused QKV projection: [4096,512] @ [512,1536]
        split_kernel<<<n4_x / 256, 256>>>(x, ahi, alo, n4_x);
        gemm_mma_kernel<false, false><<<gQKV, 128, GM_SMEM_B>>>(
            ahi, alo, wqkvh, wqkvl, nullptr, qkv, ROWS, 3 * DD, DD);

        attn_kernel<<<gA, 256, ATTN_SMEM_BYTES>>>(qkv, o);

        // Output projection
        split_kernel<<<n4_x / 256, 256>>>(o, ahi, alo, n4_x);
        gemm_mma_kernel<false, false><<<gD, 128, GM_SMEM_B>>>(
            ahi, alo, woh, wol, nullptr, t, ROWS, DD, DD);
        add_ln_kernel<<<ROWS, 256>>>(t, x, ln1g + (size_t)l * DD, ln1b + (size_t)l * DD, x);

        // FFN
        split_kernel<<<n4_x / 256, 256>>>(x, ahi, alo, n4_x);
        gemm_mma_kernel<true, true><<<gF, 128, GM_SMEM_B>>>(
            ahi, alo, w1h, w1l, B1, ff, ROWS, FFN, DD);
        split_kernel<<<n4_ff / 256, 256>>>(ff, ahi, alo, n4_ff);
        gemm_mma_kernel<true, false><<<gD, 128, GM_SMEM_B>>>(
            ahi, alo, w2h, w2l, B2, t, ROWS, DD, FFN);

        float* ln2_out = (l == LL - 1) ? out : x;
        add_ln_kernel<<<ROWS, 256>>>(t, x, ln2g + (size_t)l * DD, ln2b + (size_t)l * DD, ln2_out);
    }
}

// round 4
// speedup vs baseline: 2.8655x; 1.8721x over previous
#include <cuda_runtime.h>
#include <cuda_bf16.h>
#include <math.h>
#include <stdint.h>

// Problem constants
#define BB   2
#define SS   2048
#define DD   512
#define HH   8
#define HDIM 64
#define FFN  2048
#define LL   4
#define ROWS (BB*SS)   // 4096
#define LDQKV (3*DD)   // 1536

// ---------------------------------------------------------------------------
// Scratch (no cudaMalloc allowed)
// ---------------------------------------------------------------------------
__device__ float g_x  [ROWS*DD];
__device__ float g_qkv[ROWS*3*DD];
__device__ float g_t  [ROWS*DD];

__device__ __nv_bfloat16 g_ahi[ROWS*DD];
__device__ __nv_bfloat16 g_alo[ROWS*DD];
__device__ __nv_bfloat16 g_ffh[ROWS*FFN];
__device__ __nv_bfloat16 g_ffl[ROWS*FFN];

__device__ __nv_bfloat16 g_wqkv_hi[3*DD*DD], g_wqkv_lo[3*DD*DD];
__device__ __nv_bfloat16 g_wo_hi  [DD*DD],   g_wo_lo  [DD*DD];
__device__ __nv_bfloat16 g_w1_hi  [FFN*DD],  g_w1_lo  [FFN*DD];
__device__ __nv_bfloat16 g_w2_hi  [DD*FFN],  g_w2_lo  [DD*FFN];

// ---------------------------------------------------------------------------
// PTX helpers (compute_103-safe: cp.async / ldmatrix / mma.sync only)
// ---------------------------------------------------------------------------
__device__ __forceinline__ uint32_t smem_u32(const void* p) {
    uint32_t a;
    asm("{ .reg .u64 t; cvta.to.shared.u64 t, %1; cvt.u32.u64 %0, t; }"
        : "=r"(a) : "l"(p));
    return a;
}

__device__ __forceinline__ void cpa16(uint32_t saddr, const void* gaddr) {
    asm volatile("cp.async.ca.shared.global [%0], [%1], 16;"
                 :: "r"(saddr), "l"(gaddr) : "memory");
}
__device__ __forceinline__ void cpa_commit() {
    asm volatile("cp.async.commit_group;" ::: "memory");
}
__device__ __forceinline__ void cpa_wait1() {
    asm volatile("cp.async.wait_group 1;" ::: "memory");
}
__device__ __forceinline__ void cpa_wait0() {
    asm volatile("cp.async.wait_group 0;" ::: "memory");
}

__device__ __forceinline__ void ldm_x4(uint32_t* r, uint32_t addr) {
    asm volatile("ldmatrix.sync.aligned.m8n8.x4.shared.b16 {%0,%1,%2,%3}, [%4];"
                 : "=r"(r[0]), "=r"(r[1]), "=r"(r[2]), "=r"(r[3]) : "r"(addr));
}
__device__ __forceinline__ void ldm_x4t(uint32_t* r, uint32_t addr) {
    asm volatile("ldmatrix.sync.aligned.m8n8.x4.trans.shared.b16 {%0,%1,%2,%3}, [%4];"
                 : "=r"(r[0]), "=r"(r[1]), "=r"(r[2]), "=r"(r[3]) : "r"(addr));
}

__device__ __forceinline__ void mma_bf16(float* c, const uint32_t* a,
                                         uint32_t b0, uint32_t b1) {
    asm volatile(
        "mma.sync.aligned.m16n8k16.row.col.f32.bf16.bf16.f32 "
        "{%0,%1,%2,%3}, {%4,%5,%6,%7}, {%8,%9}, {%0,%1,%2,%3};"
        : "+f"(c[0]), "+f"(c[1]), "+f"(c[2]), "+f"(c[3])
        : "r"(a[0]), "r"(a[1]), "r"(a[2]), "r"(a[3]), "r"(b0), "r"(b1));
}

__device__ __forceinline__ uint32_t bfpack(__nv_bfloat16 a, __nv_bfloat16 b) {
    __nv_bfloat162 t = __halves2bfloat162(a, b);
    return *(uint32_t*)&t;
}
__device__ __forceinline__ void split_pair(float a, float b,
                                           uint32_t& h, uint32_t& l) {
    __nv_bfloat16 ha = __float2bfloat16(a), hb = __float2bfloat16(b);
    h = bfpack(ha, hb);
    l = bfpack(__float2bfloat16(a - __bfloat162float(ha)),
               __float2bfloat16(b - __bfloat162float(hb)));
}

// ---------------------------------------------------------------------------
// Embedding + positional encoding, emits fp32 x and bf16 hi/lo
// ---------------------------------------------------------------------------
__global__ void embed_pe_kernel(const int* __restrict__ tokens,
                                const float* __restrict__ emb,
                                float* __restrict__ x,
                                __nv_bfloat16* __restrict__ xhi,
                                __nv_bfloat16* __restrict__ xlo)
{
    int r = blockIdx.x;
    int s = r % SS;
    int tok = tokens[r];
    const float* e = emb + (size_t)tok * DD;
    const float neg_ln1e4_over_d = -logf(10000.0f) / (float)DD;
    for (int i = threadIdx.x; i < DD; i += blockDim.x) {
        float freq = expf((float)(i & ~1) * neg_ln1e4_over_d);
        float ang  = (float)s * freq;
        float pe   = (i & 1) ? cosf(ang) : sinf(ang);
        float v = e[i] + pe;
        x[(size_t)r * DD + i] = v;
        __nv_bfloat16 h = __float2bfloat16(v);
        xhi[(size_t)r * DD + i] = h;
        xlo[(size_t)r * DD + i] = __float2bfloat16(v - __bfloat162float(h));
    }
}

// ---------------------------------------------------------------------------
// Weight transpose + bf16 hi/lo split: W[K,N] fp32 -> T_hi/T_lo [N,K] bf16
// ---------------------------------------------------------------------------
__global__ void transpose_split_kernel(const float* __restrict__ W,
                                       __nv_bfloat16* __restrict__ Thi,
                                       __nv_bfloat16* __restrict__ Tlo,
                                       int K, int N)
{
    __shared__ float tile[32][33];
    const int k0 = blockIdx.y * 32;
    const int n0 = blockIdx.x * 32;
    const int tx = threadIdx.x;
    const int ty = threadIdx.y;

    #pragma unroll
    for (int i = ty; i < 32; i += 8)
        tile[i][tx] = W[(size_t)(k0 + i) * N + n0 + tx];
    __syncthreads();
    #pragma unroll
    for (int i = ty; i < 32; i += 8) {
        float v = tile[tx][i];
        __nv_bfloat16 h = __float2bfloat16(v);
        __nv_bfloat16 l = __float2bfloat16(v - __bfloat162float(h));
        Thi[(size_t)(n0 + i) * K + k0 + tx] = h;
        Tlo[(size_t)(n0 + i) * K + k0 + tx] = l;
    }
}

// ---------------------------------------------------------------------------
// bf16x3 GEMM via mma.sync: C[M,N] = A[M,K] @ B^T  (B stored [N,K] K-major)
// CTA 128x128, BK=32, 4 warps (each 64x64), double-buffered cp.async.
// SPLITOUT: write bf16 hi/lo instead of fp32 C.
// ---------------------------------------------------------------------------
#define GM_PITCH_B   80
#define GM_TILE_B    (128 * GM_PITCH_B)
#define GM_STAGE_B   (4 * GM_TILE_B)
#define GM_SMEM_B    (2 * GM_STAGE_B)   // 81920

__device__ __forceinline__ void gm_load_stage(uint32_t sb, int stage,
                                              const __nv_bfloat16* __restrict__ Ahi,
                                              const __nv_bfloat16* __restrict__ Alo,
                                              const __nv_bfloat16* __restrict__ Bhi,
                                              const __nv_bfloat16* __restrict__ Blo,
                                              int m0, int n0, int kc, int K, int tid)
{
    const uint32_t sbase = sb + stage * GM_STAGE_B;
    #pragma unroll
    for (int t = 0; t < 4; t++) {
        const __nv_bfloat16* p = (t == 0) ? Ahi : (t == 1) ? Alo : (t == 2) ? Bhi : Blo;
        const int rb = (t < 2) ? m0 : n0;
        #pragma unroll
        for (int i = 0; i < 4; i++) {
            int e   = tid + i * 128;
            int row = e >> 2;
            int ch  = e & 3;
            cpa16(sbase + t * GM_TILE_B + row * GM_PITCH_B + ch * 16,
                  p + (size_t)(rb + row) * K + kc + ch * 8);
        }
    }
    cpa_commit();
}

template<bool BIAS, bool RELU, bool SPLITOUT>
__global__ __launch_bounds__(128, 2)
void gemm_mma_kernel(const __nv_bfloat16* __restrict__ Ahi,
                     const __nv_bfloat16* __restrict__ Alo,
                     const __nv_bfloat16* __restrict__ Bhi,
                     const __nv_bfloat16* __restrict__ Blo,
                     const float* __restrict__ bias,
                     float* __restrict__ C,
                     __nv_bfloat16* __restrict__ Chi,
                     __nv_bfloat16* __restrict__ Clo,
                     int M, int N, int K)
{
    extern __shared__ char smem[];
    const uint32_t sb = smem_u32(smem);
    const int tid  = threadIdx.x;
    const int lane = tid & 31;
    const int wid  = tid >> 5;
    const int wm   = wid & 1;
    const int wn   = wid >> 1;
    const int m0   = blockIdx.y * 128;
    const int n0   = blockIdx.x * 128;

    float cc[4][8][4];
    #pragma unroll
    for (int mt = 0; mt < 4; mt++)
        #pragma unroll
        for (int nt = 0; nt < 8; nt++)
            #pragma unroll
            for (int j = 0; j < 4; j++)
                cc[mt][nt][j] = 0.0f;

    const int NC = K >> 5;

    gm_load_stage(sb, 0, Ahi, Alo, Bhi, Blo, m0, n0, 0, K, tid);

    const int a_row_off = (lane & 15);
    const int a_col_off = ((lane >> 4) << 3);
    const int b_row_off = (lane & 7) + ((lane >> 4) << 3);
    const int b_col_off = (((lane >> 3) & 1) << 3);

    for (int c = 0; c < NC; c++) {
        const int s = c & 1;
        if (c + 1 < NC) {
            gm_load_stage(sb, s ^ 1, Ahi, Alo, Bhi, Blo, m0, n0, (c + 1) << 5, K, tid);
            cpa_wait1();
        } else {
            cpa_wait0();
        }
        __syncthreads();

        const uint32_t ah_b = sb + s * GM_STAGE_B + 0 * GM_TILE_B;
        const uint32_t al_b = sb + s * GM_STAGE_B + 1 * GM_TILE_B;
        const uint32_t bh_b = sb + s * GM_STAGE_B + 2 * GM_TILE_B;
        const uint32_t bl_b = sb + s * GM_STAGE_B + 3 * GM_TILE_B;

        #pragma unroll
        for (int ks = 0; ks < 2; ks++) {
            uint32_t ah[4][4], al[4][4], bh[4][4], bl[4][4];
            const int acol = (ks * 16 + a_col_off) * 2;
            const int bcol = (ks * 16 + b_col_off) * 2;
            #pragma unroll
            for (int mt = 0; mt < 4; mt++) {
                const int r = (wm * 64 + mt * 16 + a_row_off) * GM_PITCH_B;
                ldm_x4(ah[mt], ah_b + r + acol);
                ldm_x4(al[mt], al_b + r + acol);
            }
            #pragma unroll
            for (int ng = 0; ng < 4; ng++) {
                const int r = (wn * 64 + ng * 16 + b_row_off) * GM_PITCH_B;
                ldm_x4(bh[ng], bh_b + r + bcol);
                ldm_x4(bl[ng], bl_b + r + bcol);
            }
            #pragma unroll
            for (int mt = 0; mt < 4; mt++)
                #pragma unroll
                for (int nt = 0; nt < 8; nt++) {
                    const int ng = nt >> 1, o = (nt & 1) * 2;
                    mma_bf16(cc[mt][nt], ah[mt], bh[ng][o], bh[ng][o + 1]);
                    mma_bf16(cc[mt][nt], ah[mt], bl[ng][o], bl[ng][o + 1]);
                    mma_bf16(cc[mt][nt], al[mt], bh[ng][o], bh[ng][o + 1]);
                }
        }
        __syncthreads();
    }

    // Epilogue
    #pragma unroll
    for (int mt = 0; mt < 4; mt++) {
        const int r0 = m0 + wm * 64 + mt * 16 + (lane >> 2);
        #pragma unroll
        for (int nt = 0; nt < 8; nt++) {
            const int col = n0 + wn * 64 + nt * 8 + (lane & 3) * 2;
            float2 v0 = make_float2(cc[mt][nt][0], cc[mt][nt][1]);
            float2 v1 = make_float2(cc[mt][nt][2], cc[mt][nt][3]);
            if (BIAS) {
                float b0 = bias[col], b1 = bias[col + 1];
                v0.x += b0; v0.y += b1;
                v1.x += b0; v1.y += b1;
            }
            if (RELU) {
                v0.x = fmaxf(v0.x, 0.f); v0.y = fmaxf(v0.y, 0.f);
                v1.x = fmaxf(v1.x, 0.f); v1.y = fmaxf(v1.y, 0.f);
            }
            if (SPLITOUT) {
                uint32_t h, l;
                split_pair(v0.x, v0.y, h, l);
                *(uint32_t*)&Chi[(size_t)r0 * N + col] = h;
                *(uint32_t*)&Clo[(size_t)r0 * N + col] = l;
                split_pair(v1.x, v1.y, h, l);
                *(uint32_t*)&Chi[(size_t)(r0 + 8) * N + col] = h;
                *(uint32_t*)&Clo[(size_t)(r0 + 8) * N + col] = l;
            } else {
                *(float2*)&C[(size_t)r0 * N + col]       = v0;
                *(float2*)&C[(size_t)(r0 + 8) * N + col] = v1;
            }
        }
    }
}

// ---------------------------------------------------------------------------
// Flash attention via mma.sync, bf16x3 split precision.
// CTA: 128 queries x 1 (b,h), 8 warps x 16 query rows. K/V tiles of 64 keys.
// Output written directly as bf16 hi/lo (input of Wo GEMM).
// ---------------------------------------------------------------------------
#define AT_PITCH 144
#define AT_KH 0
#define AT_KL (64*AT_PITCH)
#define AT_VH (2*64*AT_PITCH)
#define AT_VL (3*64*AT_PITCH)
#define AT_SMEM (4*64*AT_PITCH)   // 36864

__global__ __launch_bounds__(256, 1)
void attn_mma_kernel(const float* __restrict__ qkv,
                     __nv_bfloat16* __restrict__ ohi,
                     __nv_bfloat16* __restrict__ olo)
{
    __shared__ __align__(16) char sm[AT_SMEM];
    const uint32_t sb = smem_u32(sm);
    const int tid  = threadIdx.x;
    const int lane = tid & 31;
    const int w    = tid >> 5;
    const int q0   = blockIdx.x * 128;
    const int bh   = blockIdx.y;
    const int b    = bh / HH;
    const int h    = bh % HH;

    // ---- Q fragments (pre-scaled by 1/8), hi/lo split, kept in registers ----
    uint32_t qh[4][4], ql[4][4];
    {
        const size_t r_lo = (size_t)(b * SS + q0 + w * 16 + (lane >> 2));
        const size_t r_hi = r_lo + 8;
        const float* qp = qkv + (size_t)h * HDIM;
        #pragma unroll
        for (int ks = 0; ks < 4; ks++) {
            const int c = ks * 16 + (lane & 3) * 2;
            float2 f[4];
            f[0] = *(const float2*)&qp[r_lo * LDQKV + c];
            f[1] = *(const float2*)&qp[r_hi * LDQKV + c];
            f[2] = *(const float2*)&qp[r_lo * LDQKV + c + 8];
            f[3] = *(const float2*)&qp[r_hi * LDQKV + c + 8];
            #pragma unroll
            for (int j = 0; j < 4; j++)
                split_pair(f[j].x * 0.125f, f[j].y * 0.125f, qh[ks][j], ql[ks][j]);
        }
    }

    float oacc[8][4];
    #pragma unroll
    for (int nt = 0; nt < 8; nt++)
        #pragma unroll
        for (int j = 0; j < 4; j++)
            oacc[nt][j] = 0.0f;
    float m_lo = -1e30f, m_hi = -1e30f, l_lo = 0.0f, l_hi = 0.0f;

    const float* kp = qkv + DD     + (size_t)h * HDIM;
    const float* vp = qkv + 2 * DD + (size_t)h * HDIM;

    const int krow  = (lane & 7) + ((lane >> 4) << 3);
    const int kcolb = ((lane >> 3) & 1) * 16;
    const int vrow  = lane & 15;
    const int vcolb = ((lane >> 4) << 3) * 2;

    for (int t0 = 0; t0 < SS; t0 += 64) {
        __syncthreads();
        // Load + convert K,V tile (64 keys x 64 dims) to bf16 hi/lo smem
        #pragma unroll
        for (int i = 0; i < 4; i++) {
            int e  = tid + i * 256;
            int r  = e >> 4;
            int c4 = (e & 15) << 2;
            size_t grow = (size_t)(b * SS + t0 + r) * LDQKV + c4;
            float4 kv = *(const float4*)&kp[grow];
            float4 vv = *(const float4*)&vp[grow];
            uint32_t h0, l0, h1, l1;
            split_pair(kv.x, kv.y, h0, l0);
            split_pair(kv.z, kv.w, h1, l1);
            uint32_t off = r * AT_PITCH + c4 * 2;
            *(uint32_t*)(sm + AT_KH + off)     = h0;
            *(uint32_t*)(sm + AT_KH + off + 4) = h1;
            *(uint32_t*)(sm + AT_KL + off)     = l0;
            *(uint32_t*)(sm + AT_KL + off + 4) = l1;
            split_pair(vv.x, vv.y, h0, l0);
            split_pair(vv.z, vv.w, h1, l1);
            *(uint32_t*)(sm + AT_VH + off)     = h0;
            *(uint32_t*)(sm + AT_VH + off + 4) = h1;
            *(uint32_t*)(sm + AT_VL + off)     = l0;
            *(uint32_t*)(sm + AT_VL + off + 4) = l1;
        }
        __syncthreads();

        // ---- S = Q K^T (3 passes) ----
        float s[8][4];
        #pragma unroll
        for (int nt = 0; nt < 8; nt++)
            #pragma unroll
            for (int j = 0; j < 4; j++)
                s[nt][j] = 0.0f;

        #pragma unroll
        for (int ks = 0; ks < 4; ks++) {
            #pragma unroll
            for (int g = 0; g < 4; g++) {
                uint32_t kh[4], kl[4];
                uint32_t addr = (uint32_t)((g * 16 + krow) * AT_PITCH + ks * 32 + kcolb);
                ldm_x4(kh, sb + AT_KH + addr);
                ldm_x4(kl, sb + AT_KL + addr);
                mma_bf16(s[2*g],   qh[ks], kh[0], kh[1]);
                mma_bf16(s[2*g],   qh[ks], kl[0], kl[1]);
                mma_bf16(s[2*g],   ql[ks], kh[0], kh[1]);
                mma_bf16(s[2*g+1], qh[ks], kh[2], kh[3]);
                mma_bf16(s[2*g+1], qh[ks], kl[2], kl[3]);
                mma_bf16(s[2*g+1], ql[ks], kh[2], kh[3]);
            }
        }

        // ---- online softmax ----
        float mx0 = -1e30f, mx1 = -1e30f;
        #pragma unroll
        for (int nt = 0; nt < 8; nt++) {
            mx0 = fmaxf(mx0, fmaxf(s[nt][0], s[nt][1]));
            mx1 = fmaxf(mx1, fmaxf(s[nt][2], s[nt][3]));
        }
        mx0 = fmaxf(mx0, __shfl_xor_sync(0xFFFFFFFF, mx0, 1));
        mx0 = fmaxf(mx0, __shfl_xor_sync(0xFFFFFFFF, mx0, 2));
        mx1 = fmaxf(mx1, __shfl_xor_sync(0xFFFFFFFF, mx1, 1));
        mx1 = fmaxf(mx1, __shfl_xor_sync(0xFFFFFFFF, mx1, 2));
        float mn0 = fmaxf(m_lo, mx0), mn1 = fmaxf(m_hi, mx1);
        float a0 = __expf(m_lo - mn0), a1 = __expf(m_hi - mn1);
        m_lo = mn0; m_hi = mn1;

        float sum0 = 0.0f, sum1 = 0.0f;
        #pragma unroll
        for (int nt = 0; nt < 8; nt++) {
            s[nt][0] = __expf(s[nt][0] - mn0);
            s[nt][1] = __expf(s[nt][1] - mn0);
            s[nt][2] = __expf(s[nt][2] - mn1);
            s[nt][3] = __expf(s[nt][3] - mn1);
            sum0 += s[nt][0] + s[nt][1];
            sum1 += s[nt][2] + s[nt][3];
        }
        sum0 += __shfl_xor_sync(0xFFFFFFFF, sum0, 1);
        sum0 += __shfl_xor_sync(0xFFFFFFFF, sum0, 2);
        sum1 += __shfl_xor_sync(0xFFFFFFFF, sum1, 1);
        sum1 += __shfl_xor_sync(0xFFFFFFFF, sum1, 2);
        l_lo = l_lo * a0 + sum0;
        l_hi = l_hi * a1 + sum1;

        #pragma unroll
        for (int nt = 0; nt < 8; nt++) {
            oacc[nt][0] *= a0; oacc[nt][1] *= a0;
            oacc[nt][2] *= a1; oacc[nt][3] *= a1;
        }

        // ---- O += P V (3 passes) ----
        #pragma unroll
        for (int ks = 0; ks < 4; ks++) {
            uint32_t ph[4], pl[4];
            split_pair(s[2*ks][0],   s[2*ks][1],   ph[0], pl[0]);
            split_pair(s[2*ks][2],   s[2*ks][3],   ph[1], pl[1]);
            split_pair(s[2*ks+1][0], s[2*ks+1][1], ph[2], pl[2]);
            split_pair(s[2*ks+1][2], s[2*ks+1][3], ph[3], pl[3]);
            #pragma unroll
            for (int g = 0; g < 4; g++) {
                uint32_t vh[4], vl[4];
                uint32_t addr = (uint32_t)((ks * 16 + vrow) * AT_PITCH + g * 32 + vcolb);
                ldm_x4t(vh, sb + AT_VH + addr);
                ldm_x4t(vl, sb + AT_VL + addr);
                mma_bf16(oacc[2*g],   ph, vh[0], vh[1]);
                mma_bf16(oacc[2*g],   ph, vl[0], vl[1]);
                mma_bf16(oacc[2*g],   pl, vh[0], vh[1]);
                mma_bf16(oacc[2*g+1], ph, vh[2], vh[3]);
                mma_bf16(oacc[2*g+1], ph, vl[2], vl[3]);
                mma_bf16(oacc[2*g+1], pl, vh[2], vh[3]);
            }
        }
    }

    // ---- epilogue: normalize, split, store bf16 hi/lo ----
    const float il0 = 1.0f / l_lo, il1 = 1.0f / l_hi;
    const size_t row0 = (size_t)(b * SS + q0 + w * 16 + (lane >> 2));
    #pragma unroll
    for (int nt = 0; nt < 8; nt++) {
        const int col = h * HDIM + nt * 8 + (lane & 3) * 2;
        uint32_t hh, lll;
        split_pair(oacc[nt][0] * il0, oacc[nt][1] * il0, hh, lll);
        *(uint32_t*)&ohi[row0 * DD + col] = hh;
        *(uint32_t*)&olo[row0 * DD + col] = lll;
        split_pair(oacc[nt][2] * il1, oacc[nt][3] * il1, hh, lll);
        *(uint32_t*)&ohi[(row0 + 8) * DD + col] = hh;
        *(uint32_t*)&olo[(row0 + 8) * DD + col] = lll;
    }
}

// ---------------------------------------------------------------------------
// out = LayerNorm(a + b) * g + beta; optional bf16 hi/lo output for next GEMM
// ---------------------------------------------------------------------------
template<bool SPLIT>
__global__ __launch_bounds__(256)
void add_ln_kernel(const float* __restrict__ a,
                   const float* __restrict__ b,
                   const float* __restrict__ g,
                   const float* __restrict__ beta,
                   float* __restrict__ out,
                   __nv_bfloat16* __restrict__ ohi,
                   __nv_bfloat16* __restrict__ olo)
{
    __shared__ float red[256];
    const int tid = threadIdx.x;
    const size_t r = blockIdx.x;

    float v0 = a[r * DD + tid]       + b[r * DD + tid];
    float v1 = a[r * DD + tid + 256] + b[r * DD + tid + 256];

    red[tid] = v0 + v1;
    __syncthreads();
    #pragma unroll
    for (int off = 128; off > 0; off >>= 1) {
        if (tid < off) red[tid] += red[tid + off];
        __syncthreads();
    }
    float mean = red[0] * (1.0f / (float)DD);
    __syncthreads();

    float d0 = v0 - mean, d1 = v1 - mean;
    red[tid] = d0 * d0 + d1 * d1;
    __syncthreads();
    #pragma unroll
    for (int off = 128; off > 0; off >>= 1) {
        if (tid < off) red[tid] += red[tid + off];
        __syncthreads();
    }
    float var  = red[0] * (1.0f / (float)DD);
    float rstd = rsqrtf(var + 1e-5f);

    float o0 = d0 * rstd * g[tid]       + beta[tid];
    float o1 = d1 * rstd * g[tid + 256] + beta[tid + 256];
    out[r * DD + tid]       = o0;
    out[r * DD + tid + 256] = o1;
    if (SPLIT) {
        __nv_bfloat16 h0 = __float2bfloat16(o0);
        __nv_bfloat16 h1 = __float2bfloat16(o1);
        ohi[r * DD + tid]       = h0;
        ohi[r * DD + tid + 256] = h1;
        olo[r * DD + tid]       = __float2bfloat16(o0 - __bfloat162float(h0));
        olo[r * DD + tid + 256] = __float2bfloat16(o1 - __bfloat162float(h1));
    }
}

// ---------------------------------------------------------------------------
// Launcher
// ---------------------------------------------------------------------------
extern "C" void kernel_launch(void* const* d_in, const int* in_sizes, int n_in,
                              void* d_out, int out_size)
{
    (void)in_sizes; (void)n_in; (void)out_size;

    const int*   tokens = (const int*)  d_in[0];
    const float* emb    = (const float*)d_in[1];
    const float* wq     = (const float*)d_in[2];
    const float* wk     = (const float*)d_in[3];
    const float* wv     = (const float*)d_in[4];
    const float* wo     = (const float*)d_in[5];
    const float* w1     = (const float*)d_in[6];
    const float* bf1    = (const float*)d_in[7];
    const float* w2     = (const float*)d_in[8];
    const float* bf2    = (const float*)d_in[9];
    const float* ln1g   = (const float*)d_in[10];
    const float* ln1b   = (const float*)d_in[11];
    const float* ln2g   = (const float*)d_in[12];
    const float* ln2b   = (const float*)d_in[13];
    float* out = (float*)d_out;

    float *x, *qkv, *t;
    __nv_bfloat16 *ahi, *alo, *ffh, *ffl;
    __nv_bfloat16 *wqkvh, *wqkvl, *woh, *wol, *w1h, *w1l, *w2h, *w2l;
    cudaGetSymbolAddress((void**)&x,    g_x);
    cudaGetSymbolAddress((void**)&qkv,  g_qkv);
    cudaGetSymbolAddress((void**)&t,    g_t);
    cudaGetSymbolAddress((void**)&ahi,  g_ahi);
    cudaGetSymbolAddress((void**)&alo,  g_alo);
    cudaGetSymbolAddress((void**)&ffh,  g_ffh);
    cudaGetSymbolAddress((void**)&ffl,  g_ffl);
    cudaGetSymbolAddress((void**)&wqkvh, g_wqkv_hi);
    cudaGetSymbolAddress((void**)&wqkvl, g_wqkv_lo);
    cudaGetSymbolAddress((void**)&woh,  g_wo_hi);
    cudaGetSymbolAddress((void**)&wol,  g_wo_lo);
    cudaGetSymbolAddress((void**)&w1h,  g_w1_hi);
    cudaGetSymbolAddress((void**)&w1l,  g_w1_lo);
    cudaGetSymbolAddress((void**)&w2h,  g_w2_hi);
    cudaGetSymbolAddress((void**)&w2l,  g_w2_lo);

    cudaFuncSetAttribute(gemm_mma_kernel<false, false, false>,
                         cudaFuncAttributeMaxDynamicSharedMemorySize, GM_SMEM_B);
    cudaFuncSetAttribute(gemm_mma_kernel<true, true, true>,
                         cudaFuncAttributeMaxDynamicSharedMemorySize, GM_SMEM_B);
    cudaFuncSetAttribute(gemm_mma_kernel<true, false, false>,
                         cudaFuncAttributeMaxDynamicSharedMemorySize, GM_SMEM_B);

    embed_pe_kernel<<<ROWS, 256>>>(tokens, emb, x, ahi, alo);

    const dim3 tsB(32, 8);
    const dim3 gQKV(3 * DD / 128, ROWS / 128);  // (12, 32)
    const dim3 gD(DD / 128, ROWS / 128);        // (4, 32)
    const dim3 gF(FFN / 128, ROWS / 128);       // (16, 32)
    const dim3 gA(SS / 128, BB * HH);           // (16, 16)

    for (int l = 0; l < LL; l++) {
        const float* Wq = wq + (size_t)l * DD * DD;
        const float* Wk = wk + (size_t)l * DD * DD;
        const float* Wv = wv + (size_t)l * DD * DD;
        const float* Wo = wo + (size_t)l * DD * DD;
        const float* W1 = w1 + (size_t)l * DD * FFN;
        const float* B1 = bf1 + (size_t)l * FFN;
        const float* W2 = w2 + (size_t)l * FFN * DD;
        const float* B2 = bf2 + (size_t)l * DD;

        transpose_split_kernel<<<dim3(16, 16), tsB>>>(Wq, wqkvh,           wqkvl,           DD, DD);
        transpose_split_kernel<<<dim3(16, 16), tsB>>>(Wk, wqkvh + DD*DD,   wqkvl + DD*DD,   DD, DD);
        transpose_split_kernel<<<dim3(16, 16), tsB>>>(Wv, wqkvh + 2*DD*DD, wqkvl + 2*DD*DD, DD, DD);
        transpose_split_kernel<<<dim3(16, 16), tsB>>>(Wo, woh,             wol,             DD, DD);
        transpose_split_kernel<<<dim3(64, 16), tsB>>>(W1, w1h,             w1l,             DD, FFN);
        transpose_split_kernel<<<dim3(16, 64), tsB>>>(W2, w2h,             w2l,             FFN, DD);

        // Fused QKV projection
        gemm_mma_kernel<false, false, false><<<gQKV, 128, GM_SMEM_B>>>(
            ahi, alo, wqkvh, wqkvl, nullptr, qkv, nullptr, nullptr, ROWS, 3 * DD, DD);

        // Flash attention -> bf16 hi/lo output (Wo input)
        attn_mma_kernel<<<gA, 256>>>(qkv, ahi, alo);

        // Output projection
        gemm_mma_kernel<false, false, false><<<gD, 128, GM_SMEM_B>>>(
            ahi, alo, woh, wol, nullptr, t, nullptr, nullptr, ROWS, DD, DD);
        add_ln_kernel<true><<<ROWS, 256>>>(
            t, x, ln1g + (size_t)l * DD, ln1b + (size_t)l * DD, x, ahi, alo);

        // FFN
        gemm_mma_kernel<true, true, true><<<gF, 128, GM_SMEM_B>>>(
            ahi, alo, w1h, w1l, B1, nullptr, ffh, ffl, ROWS, FFN, DD);
        gemm_mma_kernel<true, false, false><<<gD, 128, GM_SMEM_B>>>(
            ffh, ffl, w2h, w2l, B2, t, nullptr, nullptr, ROWS, DD, FFN);

        if (l == LL - 1) {
            add_ln_kernel<false><<<ROWS, 256>>>(
                t, x, ln2g + (size_t)l * DD, ln2b + (size_t)l * DD, out, nullptr, nullptr);
        } else {
            add_ln_kernel<true><<<ROWS, 256>>>(
                t, x, ln2g + (size_t)l * DD, ln2b + (size_t)l * DD, x, ahi, alo);
        }
    }
}

// round 5
// speedup vs baseline: 3.1494x; 1.0991x over previous
#include <cuda_runtime.h>
#include <cuda_bf16.h>
#include <math.h>
#include <stdint.h>

// Problem constants
#define BB   2
#define SS   2048
#define DD   512
#define HH   8
#define HDIM 64
#define FFN  2048
#define LL   4
#define ROWS (BB*SS)   // 4096
#define LDQKV (3*DD)   // 1536

// ---------------------------------------------------------------------------
// Scratch (no cudaMalloc allowed)
// ---------------------------------------------------------------------------
__device__ float g_x [ROWS*DD];
__device__ float g_t [ROWS*DD];

__device__ __nv_bfloat16 g_qkvh[ROWS*3*DD];
__device__ __nv_bfloat16 g_qkvl[ROWS*3*DD];
__device__ __nv_bfloat16 g_ahi[ROWS*DD];
__device__ __nv_bfloat16 g_alo[ROWS*DD];
__device__ __nv_bfloat16 g_ffh[ROWS*FFN];
__device__ __nv_bfloat16 g_ffl[ROWS*FFN];

// Per-layer prepped weights (transposed + hi/lo split)
__device__ __nv_bfloat16 g_wqkv_hi[LL*3*DD*DD], g_wqkv_lo[LL*3*DD*DD];
__device__ __nv_bfloat16 g_wo_hi  [LL*DD*DD],   g_wo_lo  [LL*DD*DD];
__device__ __nv_bfloat16 g_w1_hi  [LL*FFN*DD],  g_w1_lo  [LL*FFN*DD];
__device__ __nv_bfloat16 g_w2_hi  [LL*DD*FFN],  g_w2_lo  [LL*DD*FFN];

// ---------------------------------------------------------------------------
// PTX helpers (compute_103-safe: cp.async / ldmatrix / mma.sync only)
// ---------------------------------------------------------------------------
__device__ __forceinline__ uint32_t smem_u32(const void* p) {
    uint32_t a;
    asm("{ .reg .u64 t; cvta.to.shared.u64 t, %1; cvt.u32.u64 %0, t; }"
        : "=r"(a) : "l"(p));
    return a;
}

__device__ __forceinline__ void cpa16(uint32_t saddr, const void* gaddr) {
    asm volatile("cp.async.ca.shared.global [%0], [%1], 16;"
                 :: "r"(saddr), "l"(gaddr) : "memory");
}
__device__ __forceinline__ void cpa_commit() {
    asm volatile("cp.async.commit_group;" ::: "memory");
}
__device__ __forceinline__ void cpa_wait1() {
    asm volatile("cp.async.wait_group 1;" ::: "memory");
}
__device__ __forceinline__ void cpa_wait0() {
    asm volatile("cp.async.wait_group 0;" ::: "memory");
}

__device__ __forceinline__ void ldm_x4(uint32_t* r, uint32_t addr) {
    asm volatile("ldmatrix.sync.aligned.m8n8.x4.shared.b16 {%0,%1,%2,%3}, [%4];"
                 : "=r"(r[0]), "=r"(r[1]), "=r"(r[2]), "=r"(r[3]) : "r"(addr));
}
__device__ __forceinline__ void ldm_x4t(uint32_t* r, uint32_t addr) {
    asm volatile("ldmatrix.sync.aligned.m8n8.x4.trans.shared.b16 {%0,%1,%2,%3}, [%4];"
                 : "=r"(r[0]), "=r"(r[1]), "=r"(r[2]), "=r"(r[3]) : "r"(addr));
}

__device__ __forceinline__ void mma_bf16(float* c, const uint32_t* a,
                                         uint32_t b0, uint32_t b1) {
    asm volatile(
        "mma.sync.aligned.m16n8k16.row.col.f32.bf16.bf16.f32 "
        "{%0,%1,%2,%3}, {%4,%5,%6,%7}, {%8,%9}, {%0,%1,%2,%3};"
        : "+f"(c[0]), "+f"(c[1]), "+f"(c[2]), "+f"(c[3])
        : "r"(a[0]), "r"(a[1]), "r"(a[2]), "r"(a[3]), "r"(b0), "r"(b1));
}

__device__ __forceinline__ uint32_t bfpack(__nv_bfloat16 a, __nv_bfloat16 b) {
    __nv_bfloat162 t = __halves2bfloat162(a, b);
    return *(uint32_t*)&t;
}
__device__ __forceinline__ void split_pair(float a, float b,
                                           uint32_t& h, uint32_t& l) {
    __nv_bfloat16 ha = __float2bfloat16(a), hb = __float2bfloat16(b);
    h = bfpack(ha, hb);
    l = bfpack(__float2bfloat16(a - __bfloat162float(ha)),
               __float2bfloat16(b - __bfloat162float(hb)));
}

// ---------------------------------------------------------------------------
// Embedding + positional encoding, emits fp32 x and bf16 hi/lo
// ---------------------------------------------------------------------------
__global__ void embed_pe_kernel(const int* __restrict__ tokens,
                                const float* __restrict__ emb,
                                float* __restrict__ x,
                                __nv_bfloat16* __restrict__ xhi,
                                __nv_bfloat16* __restrict__ xlo)
{
    int r = blockIdx.x;
    int s = r % SS;
    int tok = tokens[r];
    const float* e = emb + (size_t)tok * DD;
    const float neg_ln1e4_over_d = -logf(10000.0f) / (float)DD;
    for (int i = threadIdx.x; i < DD; i += blockDim.x) {
        float freq = expf((float)(i & ~1) * neg_ln1e4_over_d);
        float ang  = (float)s * freq;
        float pe   = (i & 1) ? cosf(ang) : sinf(ang);
        float v = e[i] + pe;
        x[(size_t)r * DD + i] = v;
        __nv_bfloat16 h = __float2bfloat16(v);
        xhi[(size_t)r * DD + i] = h;
        xlo[(size_t)r * DD + i] = __float2bfloat16(v - __bfloat162float(h));
    }
}

// ---------------------------------------------------------------------------
// ONE batched kernel: transpose + hi/lo split ALL weights, ALL layers.
// Flat grid: per layer 3072 blocks (wq/wk/wv/wo: 256 each, w1: 1024, w2: 1024)
// ---------------------------------------------------------------------------
__global__ void prep_weights_kernel(const float* __restrict__ wq,
                                    const float* __restrict__ wk,
                                    const float* __restrict__ wv,
                                    const float* __restrict__ wo,
                                    const float* __restrict__ w1,
                                    const float* __restrict__ w2,
                                    __nv_bfloat16* __restrict__ wqkvh,
                                    __nv_bfloat16* __restrict__ wqkvl,
                                    __nv_bfloat16* __restrict__ woh,
                                    __nv_bfloat16* __restrict__ wol,
                                    __nv_bfloat16* __restrict__ w1h,
                                    __nv_bfloat16* __restrict__ w1l,
                                    __nv_bfloat16* __restrict__ w2h,
                                    __nv_bfloat16* __restrict__ w2l)
{
    __shared__ float tile[32][33];
    const int bid   = blockIdx.x;
    const int layer = bid / 3072;
    const int r     = bid % 3072;

    const float* src;
    __nv_bfloat16 *dh, *dl;
    int K, N, bx, by;

    if (r < 1024) {
        const int which = r >> 8;
        const int bi    = r & 255;
        bx = bi & 15; by = bi >> 4; K = DD; N = DD;
        if      (which == 0) src = wq + (size_t)layer * DD * DD;
        else if (which == 1) src = wk + (size_t)layer * DD * DD;
        else if (which == 2) src = wv + (size_t)layer * DD * DD;
        else                 src = wo + (size_t)layer * DD * DD;
        if (which < 3) {
            dh = wqkvh + (size_t)layer * 3 * DD * DD + (size_t)which * DD * DD;
            dl = wqkvl + (size_t)layer * 3 * DD * DD + (size_t)which * DD * DD;
        } else {
            dh = woh + (size_t)layer * DD * DD;
            dl = wol + (size_t)layer * DD * DD;
        }
    } else if (r < 2048) {
        const int bi = r - 1024;
        bx = bi & 63; by = bi >> 6; K = DD; N = FFN;
        src = w1 + (size_t)layer * DD * FFN;
        dh  = w1h + (size_t)layer * FFN * DD;
        dl  = w1l + (size_t)layer * FFN * DD;
    } else {
        const int bi = r - 2048;
        bx = bi & 15; by = bi >> 4; K = FFN; N = DD;
        src = w2 + (size_t)layer * FFN * DD;
        dh  = w2h + (size_t)layer * DD * FFN;
        dl  = w2l + (size_t)layer * DD * FFN;
    }

    const int k0 = by * 32;
    const int n0 = bx * 32;
    const int tx = threadIdx.x;
    const int ty = threadIdx.y;

    #pragma unroll
    for (int i = ty; i < 32; i += 8)
        tile[i][tx] = src[(size_t)(k0 + i) * N + n0 + tx];
    __syncthreads();
    #pragma unroll
    for (int i = ty; i < 32; i += 8) {
        float v = tile[tx][i];
        __nv_bfloat16 h = __float2bfloat16(v);
        __nv_bfloat16 l = __float2bfloat16(v - __bfloat162float(h));
        dh[(size_t)(n0 + i) * K + k0 + tx] = h;
        dl[(size_t)(n0 + i) * K + k0 + tx] = l;
    }
}

// ---------------------------------------------------------------------------
// bf16x3 GEMM via mma.sync: C[M,N] = A[M,K] @ B^T  (B stored [N,K] K-major)
// CTA 128x128, BK=32, 4 warps (each 64x64), double-buffered cp.async.
// SPLITOUT: write bf16 hi/lo instead of fp32 C.
// ---------------------------------------------------------------------------
#define GM_PITCH_B   80
#define GM_TILE_B    (128 * GM_PITCH_B)
#define GM_STAGE_B   (4 * GM_TILE_B)
#define GM_SMEM_B    (2 * GM_STAGE_B)   // 81920

__device__ __forceinline__ void gm_load_stage(uint32_t sb, int stage,
                                              const __nv_bfloat16* __restrict__ Ahi,
                                              const __nv_bfloat16* __restrict__ Alo,
                                              const __nv_bfloat16* __restrict__ Bhi,
                                              const __nv_bfloat16* __restrict__ Blo,
                                              int m0, int n0, int kc, int K, int tid)
{
    const uint32_t sbase = sb + stage * GM_STAGE_B;
    #pragma unroll
    for (int t = 0; t < 4; t++) {
        const __nv_bfloat16* p = (t == 0) ? Ahi : (t == 1) ? Alo : (t == 2) ? Bhi : Blo;
        const int rb = (t < 2) ? m0 : n0;
        #pragma unroll
        for (int i = 0; i < 4; i++) {
            int e   = tid + i * 128;
            int row = e >> 2;
            int ch  = e & 3;
            cpa16(sbase + t * GM_TILE_B + row * GM_PITCH_B + ch * 16,
                  p + (size_t)(rb + row) * K + kc + ch * 8);
        }
    }
    cpa_commit();
}

template<bool BIAS, bool RELU, bool SPLITOUT>
__global__ __launch_bounds__(128, 2)
void gemm_mma_kernel(const __nv_bfloat16* __restrict__ Ahi,
                     const __nv_bfloat16* __restrict__ Alo,
                     const __nv_bfloat16* __restrict__ Bhi,
                     const __nv_bfloat16* __restrict__ Blo,
                     const float* __restrict__ bias,
                     float* __restrict__ C,
                     __nv_bfloat16* __restrict__ Chi,
                     __nv_bfloat16* __restrict__ Clo,
                     int M, int N, int K)
{
    extern __shared__ char smem[];
    const uint32_t sb = smem_u32(smem);
    const int tid  = threadIdx.x;
    const int lane = tid & 31;
    const int wid  = tid >> 5;
    const int wm   = wid & 1;
    const int wn   = wid >> 1;
    const int m0   = blockIdx.y * 128;
    const int n0   = blockIdx.x * 128;

    float cc[4][8][4];
    #pragma unroll
    for (int mt = 0; mt < 4; mt++)
        #pragma unroll
        for (int nt = 0; nt < 8; nt++)
            #pragma unroll
            for (int j = 0; j < 4; j++)
                cc[mt][nt][j] = 0.0f;

    const int NC = K >> 5;

    gm_load_stage(sb, 0, Ahi, Alo, Bhi, Blo, m0, n0, 0, K, tid);

    const int a_row_off = (lane & 15);
    const int a_col_off = ((lane >> 4) << 3);
    const int b_row_off = (lane & 7) + ((lane >> 4) << 3);
    const int b_col_off = (((lane >> 3) & 1) << 3);

    for (int c = 0; c < NC; c++) {
        const int s = c & 1;
        if (c + 1 < NC) {
            gm_load_stage(sb, s ^ 1, Ahi, Alo, Bhi, Blo, m0, n0, (c + 1) << 5, K, tid);
            cpa_wait1();
        } else {
            cpa_wait0();
        }
        __syncthreads();

        const uint32_t ah_b = sb + s * GM_STAGE_B + 0 * GM_TILE_B;
        const uint32_t al_b = sb + s * GM_STAGE_B + 1 * GM_TILE_B;
        const uint32_t bh_b = sb + s * GM_STAGE_B + 2 * GM_TILE_B;
        const uint32_t bl_b = sb + s * GM_STAGE_B + 3 * GM_TILE_B;

        #pragma unroll
        for (int ks = 0; ks < 2; ks++) {
            uint32_t ah[4][4], al[4][4], bh[4][4], bl[4][4];
            const int acol = (ks * 16 + a_col_off) * 2;
            const int bcol = (ks * 16 + b_col_off) * 2;
            #pragma unroll
            for (int mt = 0; mt < 4; mt++) {
                const int r = (wm * 64 + mt * 16 + a_row_off) * GM_PITCH_B;
                ldm_x4(ah[mt], ah_b + r + acol);
                ldm_x4(al[mt], al_b + r + acol);
            }
            #pragma unroll
            for (int ng = 0; ng < 4; ng++) {
                const int r = (wn * 64 + ng * 16 + b_row_off) * GM_PITCH_B;
                ldm_x4(bh[ng], bh_b + r + bcol);
                ldm_x4(bl[ng], bl_b + r + bcol);
            }
            #pragma unroll
            for (int mt = 0; mt < 4; mt++)
                #pragma unroll
                for (int nt = 0; nt < 8; nt++) {
                    const int ng = nt >> 1, o = (nt & 1) * 2;
                    mma_bf16(cc[mt][nt], ah[mt], bh[ng][o], bh[ng][o + 1]);
                    mma_bf16(cc[mt][nt], ah[mt], bl[ng][o], bl[ng][o + 1]);
                    mma_bf16(cc[mt][nt], al[mt], bh[ng][o], bh[ng][o + 1]);
                }
        }
        __syncthreads();
    }

    // Epilogue
    #pragma unroll
    for (int mt = 0; mt < 4; mt++) {
        const int r0 = m0 + wm * 64 + mt * 16 + (lane >> 2);
        #pragma unroll
        for (int nt = 0; nt < 8; nt++) {
            const int col = n0 + wn * 64 + nt * 8 + (lane & 3) * 2;
            float2 v0 = make_float2(cc[mt][nt][0], cc[mt][nt][1]);
            float2 v1 = make_float2(cc[mt][nt][2], cc[mt][nt][3]);
            if (BIAS) {
                float b0 = bias[col], b1 = bias[col + 1];
                v0.x += b0; v0.y += b1;
                v1.x += b0; v1.y += b1;
            }
            if (RELU) {
                v0.x = fmaxf(v0.x, 0.f); v0.y = fmaxf(v0.y, 0.f);
                v1.x = fmaxf(v1.x, 0.f); v1.y = fmaxf(v1.y, 0.f);
            }
            if (SPLITOUT) {
                uint32_t h, l;
                split_pair(v0.x, v0.y, h, l);
                *(uint32_t*)&Chi[(size_t)r0 * N + col] = h;
                *(uint32_t*)&Clo[(size_t)r0 * N + col] = l;
                split_pair(v1.x, v1.y, h, l);
                *(uint32_t*)&Chi[(size_t)(r0 + 8) * N + col] = h;
                *(uint32_t*)&Clo[(size_t)(r0 + 8) * N + col] = l;
            } else {
                *(float2*)&C[(size_t)r0 * N + col]       = v0;
                *(float2*)&C[(size_t)(r0 + 8) * N + col] = v1;
            }
        }
    }
}

// ---------------------------------------------------------------------------
// Flash attention via mma.sync, bf16x3 split, bf16 hi/lo inputs via cp.async.
// CTA: 128 queries x 1 (b,h), 8 warps x 16 query rows. K/V tiles of 64 keys,
// double-buffered. Q kept in register fragments. Scale applied post-MMA.
// ---------------------------------------------------------------------------
#define AQ_PITCH  144
#define AQ_H      0
#define AQ_L      (128*AQ_PITCH)         // 18432
#define AKV_BASE  (2*128*AQ_PITCH)       // 36864
#define AKV_STAGE (4*64*AQ_PITCH)        // 36864
#define AT_SMEM   (AKV_BASE + 2*AKV_STAGE)  // 110592

__device__ __forceinline__ void attn_load_kv(uint32_t sb, int stage,
                                             const __nv_bfloat16* __restrict__ qkvh,
                                             const __nv_bfloat16* __restrict__ qkvl,
                                             int b, int h, int t0, int tid)
{
    const uint32_t sbase = sb + AKV_BASE + stage * AKV_STAGE;
    #pragma unroll
    for (int i = 0; i < 8; i++) {
        int e   = tid + i * 256;        // 0..2047
        int tsr = e >> 9;               // 0: KH, 1: KL, 2: VH, 3: VL
        int rem = e & 511;
        int r   = rem >> 3;             // 0..63
        int ch  = rem & 7;              // 16B chunk
        const __nv_bfloat16* src = (tsr & 1) ? qkvl : qkvh;
        const int colbase = DD * (1 + (tsr >> 1)) + h * HDIM + ch * 8;
        cpa16(sbase + tsr * (64 * AQ_PITCH) + r * AQ_PITCH + ch * 16,
              src + (size_t)(b * SS + t0 + r) * LDQKV + colbase);
    }
}

__global__ __launch_bounds__(256, 1)
void attn_mma_kernel(const __nv_bfloat16* __restrict__ qkvh,
                     const __nv_bfloat16* __restrict__ qkvl,
                     __nv_bfloat16* __restrict__ ohi,
                     __nv_bfloat16* __restrict__ olo)
{
    extern __shared__ char sm[];
    const uint32_t sb = smem_u32(sm);
    const int tid  = threadIdx.x;
    const int lane = tid & 31;
    const int w    = tid >> 5;
    const int q0   = blockIdx.x * 128;
    const int bh   = blockIdx.y;
    const int b    = bh / HH;
    const int h    = bh % HH;

    // Issue Q loads (128 rows x 64 cols, hi+lo) + KV stage 0, one cp.async group
    #pragma unroll
    for (int i = 0; i < 4; i++) {
        int e  = tid + i * 256;         // 0..1023
        int r  = e >> 3;                // 0..127
        int ch = e & 7;
        size_t grow = (size_t)(b * SS + q0 + r) * LDQKV + h * HDIM + ch * 8;
        cpa16(sb + AQ_H + r * AQ_PITCH + ch * 16, qkvh + grow);
        cpa16(sb + AQ_L + r * AQ_PITCH + ch * 16, qkvl + grow);
    }
    attn_load_kv(sb, 0, qkvh, qkvl, b, h, 0, tid);
    cpa_commit();

    uint32_t qh[4][4], ql[4][4];
    float oacc[8][4];
    #pragma unroll
    for (int nt = 0; nt < 8; nt++)
        #pragma unroll
        for (int j = 0; j < 4; j++)
            oacc[nt][j] = 0.0f;
    float m_lo = -1e30f, m_hi = -1e30f, l_lo = 0.0f, l_hi = 0.0f;

    const int krow  = (lane & 7) + ((lane >> 4) << 3);
    const int kcolb = ((lane >> 3) & 1) * 16;
    const int vrow  = lane & 15;
    const int vcolb = (lane >> 4) * 16;

    const int NT = SS / 64;   // 32

    for (int t = 0; t < NT; t++) {
        const int s = t & 1;
        cpa_wait0();
        __syncthreads();

        if (t == 0) {
            // Load Q fragments once (also applies to all later tiles)
            #pragma unroll
            for (int ks = 0; ks < 4; ks++) {
                uint32_t addr = sb + AQ_H +
                    (uint32_t)((w * 16 + (lane & 15)) * AQ_PITCH +
                               (ks * 16 + ((lane >> 4) << 3)) * 2);
                ldm_x4(qh[ks], addr);
                ldm_x4(ql[ks], addr + AQ_L);
            }
        }
        if (t + 1 < NT) {
            attn_load_kv(sb, s ^ 1, qkvh, qkvl, b, h, (t + 1) * 64, tid);
            cpa_commit();
        }

        const uint32_t kh_b = sb + AKV_BASE + s * AKV_STAGE;
        const uint32_t kl_b = kh_b + 64 * AQ_PITCH;
        const uint32_t vh_b = kh_b + 2 * 64 * AQ_PITCH;
        const uint32_t vl_b = kh_b + 3 * 64 * AQ_PITCH;

        // ---- S = Q K^T (3 passes) ----
        float sc[8][4];
        #pragma unroll
        for (int nt = 0; nt < 8; nt++)
            #pragma unroll
            for (int j = 0; j < 4; j++)
                sc[nt][j] = 0.0f;

        #pragma unroll
        for (int ks = 0; ks < 4; ks++) {
            #pragma unroll
            for (int g = 0; g < 4; g++) {
                uint32_t kh[4], kl[4];
                uint32_t addr = (uint32_t)((g * 16 + krow) * AQ_PITCH + ks * 32 + kcolb);
                ldm_x4(kh, kh_b + addr);
                ldm_x4(kl, kl_b + addr);
                mma_bf16(sc[2*g],   qh[ks], kh[0], kh[1]);
                mma_bf16(sc[2*g],   qh[ks], kl[0], kl[1]);
                mma_bf16(sc[2*g],   ql[ks], kh[0], kh[1]);
                mma_bf16(sc[2*g+1], qh[ks], kh[2], kh[3]);
                mma_bf16(sc[2*g+1], qh[ks], kl[2], kl[3]);
                mma_bf16(sc[2*g+1], ql[ks], kh[2], kh[3]);
            }
        }
        // apply 1/sqrt(HDIM)
        #pragma unroll
        for (int nt = 0; nt < 8; nt++)
            #pragma unroll
            for (int j = 0; j < 4; j++)
                sc[nt][j] *= 0.125f;

        // ---- online softmax ----
        float mx0 = -1e30f, mx1 = -1e30f;
        #pragma unroll
        for (int nt = 0; nt < 8; nt++) {
            mx0 = fmaxf(mx0, fmaxf(sc[nt][0], sc[nt][1]));
            mx1 = fmaxf(mx1, fmaxf(sc[nt][2], sc[nt][3]));
        }
        mx0 = fmaxf(mx0, __shfl_xor_sync(0xFFFFFFFF, mx0, 1));
        mx0 = fmaxf(mx0, __shfl_xor_sync(0xFFFFFFFF, mx0, 2));
        mx1 = fmaxf(mx1, __shfl_xor_sync(0xFFFFFFFF, mx1, 1));
        mx1 = fmaxf(mx1, __shfl_xor_sync(0xFFFFFFFF, mx1, 2));
        float mn0 = fmaxf(m_lo, mx0), mn1 = fmaxf(m_hi, mx1);
        float a0 = __expf(m_lo - mn0), a1 = __expf(m_hi - mn1);
        m_lo = mn0; m_hi = mn1;

        float sum0 = 0.0f, sum1 = 0.0f;
        #pragma unroll
        for (int nt = 0; nt < 8; nt++) {
            sc[nt][0] = __expf(sc[nt][0] - mn0);
            sc[nt][1] = __expf(sc[nt][1] - mn0);
            sc[nt][2] = __expf(sc[nt][2] - mn1);
            sc[nt][3] = __expf(sc[nt][3] - mn1);
            sum0 += sc[nt][0] + sc[nt][1];
            sum1 += sc[nt][2] + sc[nt][3];
        }
        sum0 += __shfl_xor_sync(0xFFFFFFFF, sum0, 1);
        sum0 += __shfl_xor_sync(0xFFFFFFFF, sum0, 2);
        sum1 += __shfl_xor_sync(0xFFFFFFFF, sum1, 1);
        sum1 += __shfl_xor_sync(0xFFFFFFFF, sum1, 2);
        l_lo = l_lo * a0 + sum0;
        l_hi = l_hi * a1 + sum1;

        #pragma unroll
        for (int nt = 0; nt < 8; nt++) {
            oacc[nt][0] *= a0; oacc[nt][1] *= a0;
            oacc[nt][2] *= a1; oacc[nt][3] *= a1;
        }

        // ---- O += P V (3 passes) ----
        #pragma unroll
        for (int ks = 0; ks < 4; ks++) {
            uint32_t ph[4], pl[4];
            split_pair(sc[2*ks][0],   sc[2*ks][1],   ph[0], pl[0]);
            split_pair(sc[2*ks][2],   sc[2*ks][3],   ph[1], pl[1]);
            split_pair(sc[2*ks+1][0], sc[2*ks+1][1], ph[2], pl[2]);
            split_pair(sc[2*ks+1][2], sc[2*ks+1][3], ph[3], pl[3]);
            #pragma unroll
            for (int g = 0; g < 4; g++) {
                uint32_t vh[4], vl[4];
                uint32_t addr = (uint32_t)((ks * 16 + vrow) * AQ_PITCH + g * 32 + vcolb);
                ldm_x4t(vh, vh_b + addr);
                ldm_x4t(vl, vl_b + addr);
                mma_bf16(oacc[2*g],   ph, vh[0], vh[1]);
                mma_bf16(oacc[2*g],   ph, vl[0], vl[1]);
                mma_bf16(oacc[2*g],   pl, vh[0], vh[1]);
                mma_bf16(oacc[2*g+1], ph, vh[2], vh[3]);
                mma_bf16(oacc[2*g+1], ph, vl[2], vl[3]);
                mma_bf16(oacc[2*g+1], pl, vh[2], vh[3]);
            }
        }
    }

    // ---- epilogue: normalize, split, store bf16 hi/lo ----
    const float il0 = 1.0f / l_lo, il1 = 1.0f / l_hi;
    const size_t row0 = (size_t)(b * SS + q0 + w * 16 + (lane >> 2));
    #pragma unroll
    for (int nt = 0; nt < 8; nt++) {
        const int col = h * HDIM + nt * 8 + (lane & 3) * 2;
        uint32_t hh, lll;
        split_pair(oacc[nt][0] * il0, oacc[nt][1] * il0, hh, lll);
        *(uint32_t*)&ohi[row0 * DD + col] = hh;
        *(uint32_t*)&olo[row0 * DD + col] = lll;
        split_pair(oacc[nt][2] * il1, oacc[nt][3] * il1, hh, lll);
        *(uint32_t*)&ohi[(row0 + 8) * DD + col] = hh;
        *(uint32_t*)&olo[(row0 + 8) * DD + col] = lll;
    }
}

// ---------------------------------------------------------------------------
// out = LayerNorm(a + b) * g + beta. Warp-per-row (D=512 -> 16 per lane).
// ---------------------------------------------------------------------------
template<bool SPLIT>
__global__ __launch_bounds__(256)
void add_ln_kernel(const float* __restrict__ a,
                   const float* __restrict__ b,
                   const float* __restrict__ g,
                   const float* __restrict__ beta,
                   float* __restrict__ out,
                   __nv_bfloat16* __restrict__ ohi,
                   __nv_bfloat16* __restrict__ olo)
{
    const int lane = threadIdx.x & 31;
    const size_t r = (size_t)blockIdx.x * 8 + (threadIdx.x >> 5);

    float v[16];
    float sum = 0.0f;
    #pragma unroll
    for (int c = 0; c < 4; c++) {
        const int col = c * 128 + lane * 4;
        float4 va = *(const float4*)&a[r * DD + col];
        float4 vb = *(const float4*)&b[r * DD + col];
        v[c*4+0] = va.x + vb.x;
        v[c*4+1] = va.y + vb.y;
        v[c*4+2] = va.z + vb.z;
        v[c*4+3] = va.w + vb.w;
        sum += v[c*4+0] + v[c*4+1] + v[c*4+2] + v[c*4+3];
    }
    #pragma unroll
    for (int o = 16; o > 0; o >>= 1) sum += __shfl_xor_sync(0xFFFFFFFF, sum, o);
    const float mean = sum * (1.0f / (float)DD);

    float var = 0.0f;
    #pragma unroll
    for (int i = 0; i < 16; i++) {
        v[i] -= mean;
        var += v[i] * v[i];
    }
    #pragma unroll
    for (int o = 16; o > 0; o >>= 1) var += __shfl_xor_sync(0xFFFFFFFF, var, o);
    const float rstd = rsqrtf(var * (1.0f / (float)DD) + 1e-5f);

    #pragma unroll
    for (int c = 0; c < 4; c++) {
        const int col = c * 128 + lane * 4;
        float4 vg = *(const float4*)&g[col];
        float4 vbt = *(const float4*)&beta[col];
        float4 o4;
        o4.x = v[c*4+0] * rstd * vg.x + vbt.x;
        o4.y = v[c*4+1] * rstd * vg.y + vbt.y;
        o4.z = v[c*4+2] * rstd * vg.z + vbt.z;
        o4.w = v[c*4+3] * rstd * vg.w + vbt.w;
        *(float4*)&out[r * DD + col] = o4;
        if (SPLIT) {
            uint32_t h0, l0, h1, l1;
            split_pair(o4.x, o4.y, h0, l0);
            split_pair(o4.z, o4.w, h1, l1);
            uint2 hh = make_uint2(h0, h1);
            uint2 ll = make_uint2(l0, l1);
            *(uint2*)&ohi[r * DD + col] = hh;
            *(uint2*)&olo[r * DD + col] = ll;
        }
    }
}

// ---------------------------------------------------------------------------
// Launcher
// ---------------------------------------------------------------------------
extern "C" void kernel_launch(void* const* d_in, const int* in_sizes, int n_in,
                              void* d_out, int out_size)
{
    (void)in_sizes; (void)n_in; (void)out_size;

    const int*   tokens = (const int*)  d_in[0];
    const float* emb    = (const float*)d_in[1];
    const float* wq     = (const float*)d_in[2];
    const float* wk     = (const float*)d_in[3];
    const float* wv     = (const float*)d_in[4];
    const float* wo     = (const float*)d_in[5];
    const float* w1     = (const float*)d_in[6];
    const float* bf1    = (const float*)d_in[7];
    const float* w2     = (const float*)d_in[8];
    const float* bf2    = (const float*)d_in[9];
    const float* ln1g   = (const float*)d_in[10];
    const float* ln1b   = (const float*)d_in[11];
    const float* ln2g   = (const float*)d_in[12];
    const float* ln2b   = (const float*)d_in[13];
    float* out = (float*)d_out;

    float *x, *t;
    __nv_bfloat16 *qkvh, *qkvl, *ahi, *alo, *ffh, *ffl;
    __nv_bfloat16 *wqkvh, *wqkvl, *woh, *wol, *w1h, *w1l, *w2h, *w2l;
    cudaGetSymbolAddress((void**)&x,    g_x);
    cudaGetSymbolAddress((void**)&t,    g_t);
    cudaGetSymbolAddress((void**)&qkvh, g_qkvh);
    cudaGetSymbolAddress((void**)&qkvl, g_qkvl);
    cudaGetSymbolAddress((void**)&ahi,  g_ahi);
    cudaGetSymbolAddress((void**)&alo,  g_alo);
    cudaGetSymbolAddress((void**)&ffh,  g_ffh);
    cudaGetSymbolAddress((void**)&ffl,  g_ffl);
    cudaGetSymbolAddress((void**)&wqkvh, g_wqkv_hi);
    cudaGetSymbolAddress((void**)&wqkvl, g_wqkv_lo);
    cudaGetSymbolAddress((void**)&woh,  g_wo_hi);
    cudaGetSymbolAddress((void**)&wol,  g_wo_lo);
    cudaGetSymbolAddress((void**)&w1h,  g_w1_hi);
    cudaGetSymbolAddress((void**)&w1l,  g_w1_lo);
    cudaGetSymbolAddress((void**)&w2h,  g_w2_hi);
    cudaGetSymbolAddress((void**)&w2l,  g_w2_lo);

    cudaFuncSetAttribute(gemm_mma_kernel<false, false, false>,
                         cudaFuncAttributeMaxDynamicSharedMemorySize, GM_SMEM_B);
    cudaFuncSetAttribute(gemm_mma_kernel<false, false, true>,
                         cudaFuncAttributeMaxDynamicSharedMemorySize, GM_SMEM_B);
    cudaFuncSetAttribute(gemm_mma_kernel<true, true, true>,
                         cudaFuncAttributeMaxDynamicSharedMemorySize, GM_SMEM_B);
    cudaFuncSetAttribute(gemm_mma_kernel<true, false, false>,
                         cudaFuncAttributeMaxDynamicSharedMemorySize, GM_SMEM_B);
    cudaFuncSetAttribute(attn_mma_kernel,
                         cudaFuncAttributeMaxDynamicSharedMemorySize, AT_SMEM);

    // All weight prep in one launch; embed in parallel conceptually (same stream)
    prep_weights_kernel<<<LL * 3072, dim3(32, 8)>>>(
        wq, wk, wv, wo, w1, w2,
        wqkvh, wqkvl, woh, wol, w1h, w1l, w2h, w2l);
    embed_pe_kernel<<<ROWS, 256>>>(tokens, emb, x, ahi, alo);

    const dim3 gQKV(3 * DD / 128, ROWS / 128);  // (12, 32)
    const dim3 gD(DD / 128, ROWS / 128);        // (4, 32)
    const dim3 gF(FFN / 128, ROWS / 128);       // (16, 32)
    const dim3 gA(SS / 128, BB * HH);           // (16, 16)

    for (int l = 0; l < LL; l++) {
        const float* B1 = bf1 + (size_t)l * FFN;
        const float* B2 = bf2 + (size_t)l * DD;

        // Fused QKV projection -> bf16 hi/lo
        gemm_mma_kernel<false, false, true><<<gQKV, 128, GM_SMEM_B>>>(
            ahi, alo, wqkvh + (size_t)l * 3 * DD * DD, wqkvl + (size_t)l * 3 * DD * DD,
            nullptr, nullptr, qkvh, qkvl, ROWS, 3 * DD, DD);

        // Flash attention -> bf16 hi/lo (Wo input)
        attn_mma_kernel<<<gA, 256, AT_SMEM>>>(qkvh, qkvl, ahi, alo);

        // Output projection
        gemm_mma_kernel<false, false, false><<<gD, 128, GM_SMEM_B>>>(
            ahi, alo, woh + (size_t)l * DD * DD, wol + (size_t)l * DD * DD,
            nullptr, t, nullptr, nullptr, ROWS, DD, DD);
        add_ln_kernel<true><<<ROWS / 8, 256>>>(
            t, x, ln1g + (size_t)l * DD, ln1b + (size_t)l * DD, x, ahi, alo);

        // FFN
        gemm_mma_kernel<true, true, true><<<gF, 128, GM_SMEM_B>>>(
            ahi, alo, w1h + (size_t)l * FFN * DD, w1l + (size_t)l * FFN * DD,
            B1, nullptr, ffh, ffl, ROWS, FFN, DD);
        gemm_mma_kernel<true, false, false><<<gD, 128, GM_SMEM_B>>>(
            ffh, ffl, w2h + (size_t)l * DD * FFN, w2l + (size_t)l * DD * FFN,
            B2, t, nullptr, nullptr, ROWS, DD, FFN);

        if (l == LL - 1) {
            add_ln_kernel<false><<<ROWS / 8, 256>>>(
                t, x, ln2g + (size_t)l * DD, ln2b + (size_t)l * DD, out, nullptr, nullptr);
        } else {
            add_ln_kernel<true><<<ROWS / 8, 256>>>(
                t, x, ln2g + (size_t)l * DD, ln2b + (size_t)l * DD, x, ahi, alo);
        }
    }
}